// round 8
// baseline (speedup 1.0000x reference)
#include <cuda_runtime.h>
#include <cuda_bf16.h>
#include <stdint.h>
#include <math.h>

// ---------------- problem dims ----------------
#define MDIM 8192      // B*S
#define HDIM 1024
#define RDIM 2048
#define SDIM 2048
#define NPROJ 12288    // 6 * 2048 stacked projection outputs (GEMM1 N)
#define PW 6144        // P width after pair fusion: f | q | gc
#define KOUT 4096      // R + L for the output GEMM
#define NCH 64         // scan chunks
#define CH 32          // tokens per chunk

// ---------------- scratch (device globals) ----------------
__device__ float          g_P   [(size_t)MDIM * PW];              // f | q | gc
__device__ __nv_bfloat16  g_xhi [(size_t)MDIM * HDIM];
__device__ __nv_bfloat16  g_xlo [(size_t)MDIM * HDIM];
__device__ __nv_bfloat16  g_w6hi[(size_t)NPROJ * HDIM];
__device__ __nv_bfloat16  g_w6lo[(size_t)NPROJ * HDIM];
__device__ __nv_bfloat16  g_wohi[(size_t)HDIM * KOUT];
__device__ __nv_bfloat16  g_wolo[(size_t)HDIM * KOUT];
__device__ __nv_bfloat16  g_a2hi[(size_t)MDIM * KOUT];            // [ro | h]
__device__ __nv_bfloat16  g_a2lo[(size_t)MDIM * KOUT];
__device__ float          g_Fc  [(size_t)4 * NCH * RDIM];
__device__ float          g_Gc  [(size_t)4 * NCH * RDIM];
__device__ float          g_Sc  [(size_t)4 * NCH * RDIM];

// ---------------- helpers ----------------
__device__ __forceinline__ uint32_t smem_u32(const void* p) {
    uint32_t a;
    asm("{ .reg .u64 t; cvta.to.shared.u64 t, %1; cvt.u32.u64 %0, t; }" : "=r"(a) : "l"(p));
    return a;
}
__device__ __forceinline__ void cp16(uint32_t s, const void* g) {
    asm volatile("cp.async.cg.shared.global [%0], [%1], 16;" :: "r"(s), "l"(g));
}
#define CP_COMMIT() asm volatile("cp.async.commit_group;" ::: "memory")
template<int N> __device__ __forceinline__ void cp_wait() {
    asm volatile("cp.async.wait_group %0;" :: "n"(N) : "memory");
}

__device__ __forceinline__ void ldm_x4(uint32_t (&d)[4], uint32_t a) {
    asm volatile("ldmatrix.sync.aligned.m8n8.x4.shared.b16 {%0,%1,%2,%3}, [%4];"
        : "=r"(d[0]), "=r"(d[1]), "=r"(d[2]), "=r"(d[3]) : "r"(a));
}
__device__ __forceinline__ void mma_bf16(float (&c)[4], const uint32_t (&a)[4], const uint32_t* b) {
    asm volatile("mma.sync.aligned.m16n8k16.row.col.f32.bf16.bf16.f32 "
        "{%0,%1,%2,%3}, {%4,%5,%6,%7}, {%8,%9}, {%0,%1,%2,%3};"
        : "+f"(c[0]), "+f"(c[1]), "+f"(c[2]), "+f"(c[3])
        : "r"(a[0]), "r"(a[1]), "r"(a[2]), "r"(a[3]), "r"(b[0]), "r"(b[1]));
}

// ---------------- activations ----------------
#define ACT_NONE 0
#define ACT_TANH 1
#define ACT_GC 4     // pair: sigmoid(even) * silu(odd)   -> P (single col)
#define ACT_H  5     // pair: even * silu(odd)            -> a2 split bf16

__device__ __forceinline__ float act_apply(float x, int act) {
    if (act == ACT_TANH) return tanhf(x);
    return x;
}
__device__ __forceinline__ float silu_f(float x) { return x / (1.0f + __expf(-x)); }
__device__ __forceinline__ float pair_act(float a, float b, int act) {
    if (act == ACT_GC) return (1.0f / (1.0f + __expf(-a))) * silu_f(b);
    return a * silu_f(b);   // ACT_H
}
__device__ __forceinline__ void split_bf16(float v, __nv_bfloat16& hi, __nv_bfloat16& lo) {
    hi = __float2bfloat16(v);
    lo = __float2bfloat16(v - __bfloat162float(hi));
}

// ================= HMMA bf16 3-pass split GEMM =================
// C[M,N] = act(A*B^T), A ~ Ahi+Alo, B ~ Bhi+Blo; keep AhiBhi + AloBhi + AhiBlo.
// CTA BM_ x 128, 128 threads (4 warps, each BM_ x 32), KC=32, 2-stage
// cp.async, OCC CTAs/SM.
#define BN 128
#define KC 32
#define RSTR 80         // 64B row + 16B pad (20-bank stride, conflict-free)

template<int BM_, int MI, int OCC>
__global__ void __launch_bounds__(128, OCC)
gemm_hmma(const __nv_bfloat16* __restrict__ Ahi, const __nv_bfloat16* __restrict__ Alo,
          const __nv_bfloat16* __restrict__ Bhi, const __nv_bfloat16* __restrict__ Blo,
          int K, float* __restrict__ C, int ldc,
          __nv_bfloat16* __restrict__ auxhi, __nv_bfloat16* __restrict__ auxlo,
          unsigned actlut)
{
    constexpr uint32_t OFF_AH = 0;
    constexpr uint32_t OFF_AL = BM_ * RSTR;
    constexpr uint32_t OFF_BH = 2 * BM_ * RSTR;
    constexpr uint32_t OFF_BL = (2 * BM_ + 128) * RSTR;
    constexpr uint32_t SB     = (2 * BM_ + 256) * RSTR;

    extern __shared__ char smem[];
    const uint32_t sbase = smem_u32(smem);
    const int tid  = threadIdx.x;
    const int bm   = blockIdx.y, bn = blockIdx.x;
    const int wn   = tid >> 5, lane = tid & 31;     // 4 warps in 1x4

    const __nv_bfloat16* sA0 = Ahi + (size_t)bm * BM_ * K;
    const __nv_bfloat16* sA1 = Alo + (size_t)bm * BM_ * K;
    const __nv_bfloat16* sB0 = Bhi + (size_t)bn * BN * K;
    const __nv_bfloat16* sB1 = Blo + (size_t)bn * BN * K;

    const int lcol  = tid & 3;          // 16B chunk within 64B row
    const int lrow0 = tid >> 2;         // 0..31

    auto load_stage = [&](int s) {
        const uint32_t sb = sbase + (uint32_t)(s & 1) * SB + lcol * 16;
        const int k0 = s * KC + lcol * 8;
#pragma unroll
        for (int i = 0; i < BM_ / 32; i++) {  // A hi/lo: BM_ rows each
            int row = lrow0 + 32 * i;
            cp16(sb + OFF_AH + row * RSTR, sA0 + (size_t)row * K + k0);
            cp16(sb + OFF_AL + row * RSTR, sA1 + (size_t)row * K + k0);
        }
#pragma unroll
        for (int i = 0; i < 4; i++) {         // B hi/lo: 128 rows each
            int row = lrow0 + 32 * i;
            cp16(sb + OFF_BH + row * RSTR, sB0 + (size_t)row * K + k0);
            cp16(sb + OFF_BL + row * RSTR, sB1 + (size_t)row * K + k0);
        }
    };

    // ldmatrix lane address geometry
    const int quad = lane >> 3, r8 = lane & 7;
    const uint32_t aoff = (uint32_t)((r8 + (quad & 1) * 8) * RSTR + (quad >> 1) * 16);
    const uint32_t boff = (uint32_t)((wn * 32 + r8 + (quad >> 1) * 8) * RSTR + (quad & 1) * 16);

    float acc[MI][4][4];
#pragma unroll
    for (int mi = 0; mi < MI; mi++)
#pragma unroll
        for (int nj = 0; nj < 4; nj++)
#pragma unroll
            for (int e = 0; e < 4; e++) acc[mi][nj][e] = 0.0f;

    const int ns = K / KC;
    load_stage(0); CP_COMMIT();

    for (int s = 0; s < ns; s++) {
        if (s + 1 < ns) load_stage(s + 1);
        CP_COMMIT();
        cp_wait<1>();
        __syncthreads();

        const uint32_t st = sbase + (uint32_t)(s & 1) * SB;
        const uint32_t aH = st + OFF_AH + aoff;
        const uint32_t aL = st + OFF_AL + aoff;
        const uint32_t bH = st + OFF_BH + boff;
        const uint32_t bL = st + OFF_BL + boff;

#pragma unroll
        for (int ks = 0; ks < 2; ks++) {
            const uint32_t kb = ks * 32;
            uint32_t afh[MI][4], bf[4][2];

            // A-hi fragments (MI x m16)
#pragma unroll
            for (int mi = 0; mi < MI; mi++) ldm_x4(afh[mi], aH + mi * (16 * RSTR) + kb);
            // B-hi fragments (4 x n8 via 2 x4-loads)
#pragma unroll
            for (int t = 0; t < 2; t++) {
                uint32_t tt[4];
                ldm_x4(tt, bH + t * (16 * RSTR) + kb);
                bf[2 * t][0] = tt[0]; bf[2 * t][1] = tt[1];
                bf[2 * t + 1][0] = tt[2]; bf[2 * t + 1][1] = tt[3];
            }
            // pass 1: Ahi * Bhi
#pragma unroll
            for (int mi = 0; mi < MI; mi++)
#pragma unroll
                for (int nj = 0; nj < 4; nj++) mma_bf16(acc[mi][nj], afh[mi], bf[nj]);
            // pass 2: Alo * Bhi
            {
                uint32_t afl[MI][4];
#pragma unroll
                for (int mi = 0; mi < MI; mi++) ldm_x4(afl[mi], aL + mi * (16 * RSTR) + kb);
#pragma unroll
                for (int mi = 0; mi < MI; mi++)
#pragma unroll
                    for (int nj = 0; nj < 4; nj++) mma_bf16(acc[mi][nj], afl[mi], bf[nj]);
            }
            // B-lo fragments (overwrite bf)
#pragma unroll
            for (int t = 0; t < 2; t++) {
                uint32_t tt[4];
                ldm_x4(tt, bL + t * (16 * RSTR) + kb);
                bf[2 * t][0] = tt[0]; bf[2 * t][1] = tt[1];
                bf[2 * t + 1][0] = tt[2]; bf[2 * t + 1][1] = tt[3];
            }
            // pass 3: Ahi * Blo
#pragma unroll
            for (int mi = 0; mi < MI; mi++)
#pragma unroll
                for (int nj = 0; nj < 4; nj++) mma_bf16(acc[mi][nj], afh[mi], bf[nj]);
        }
        __syncthreads();
    }

    // ---- epilogue ----
    const int region = (bn * BN) >> 11;                 // 2048-col region index
    const int act    = (int)((actlut >> (region * 4)) & 15u);
    const int row0   = bm * BM_ + (lane >> 2);

    if (act < 4) {
        // direct regions (f, q for GEMM1; everything for GEMM2): global col == C col
        const int col0 = bn * BN + wn * 32 + 2 * (lane & 3);
#pragma unroll
        for (int mi = 0; mi < MI; mi++) {
#pragma unroll
            for (int nj = 0; nj < 4; nj++) {
                float2 v0, v1;
                v0.x = act_apply(acc[mi][nj][0], act);
                v0.y = act_apply(acc[mi][nj][1], act);
                v1.x = act_apply(acc[mi][nj][2], act);
                v1.y = act_apply(acc[mi][nj][3], act);
                size_t base = (size_t)(row0 + mi * 16) * ldc + col0 + nj * 8;
                *(float2*)(C + base)                   = v0;
                *(float2*)(C + base + (size_t)8 * ldc) = v1;
            }
        }
    } else {
        // pair regions: even/odd columns combined in-thread.
        // Pair-block base: gc spans GEMM cols [4096,8192) -> pair cols 0..2047;
        // h spans [8192,12288) -> pair cols 0..2047. Base derived from ACT,
        // not from the 2048-region index (gc/h each span TWO regions).
        const int pcbase = ((bn * BN) >> 1) - ((act == ACT_GC) ? 2048 : 4096);
        const int pc0 = pcbase + wn * 16 + (lane & 3);
#pragma unroll
        for (int mi = 0; mi < MI; mi++) {
#pragma unroll
            for (int nj = 0; nj < 4; nj++) {
                float v0 = pair_act(acc[mi][nj][0], acc[mi][nj][1], act);
                float v1 = pair_act(acc[mi][nj][2], acc[mi][nj][3], act);
                int pc = pc0 + nj * 4;
                int r  = row0 + mi * 16;
                if (act == ACT_GC) {
                    C[(size_t)r * ldc + 4096 + pc]       = v0;  // gc at P cols 4096..6144
                    C[(size_t)(r + 8) * ldc + 4096 + pc] = v1;
                } else {
                    __nv_bfloat16 h0, l0, h1, l1;
                    split_bf16(v0, h0, l0);
                    split_bf16(v1, h1, l1);
                    size_t i0 = (size_t)r * KOUT + 2048 + pc;         // h at a2 cols 2048..4096
                    size_t i1 = (size_t)(r + 8) * KOUT + 2048 + pc;
                    auxhi[i0] = h0; auxlo[i0] = l0;
                    auxhi[i1] = h1; auxlo[i1] = l1;
                }
            }
        }
    }
}

// ================= conversion kernels =================
__global__ void conv_x_kernel(const float* __restrict__ x,
                              __nv_bfloat16* __restrict__ hi, __nv_bfloat16* __restrict__ lo) {
    size_t i = (size_t)blockIdx.x * blockDim.x + threadIdx.x;
    split_bf16(x[i], hi[i], lo[i]);
}

// W6 stacking: [f(0:2048) | q(2048:4096) | g:c interleaved(4096:8192) | up:gate interleaved(8192:12288)]
__global__ void conv_w6_kernel(const float* __restrict__ Wf, const float* __restrict__ Wi,
                               const float* __restrict__ Wv, const float* __restrict__ Wq,
                               const float* __restrict__ Wup, const float* __restrict__ Wg,
                               __nv_bfloat16* __restrict__ hi, __nv_bfloat16* __restrict__ lo) {
    size_t i = (size_t)blockIdx.x * blockDim.x + threadIdx.x;     // [0, 12288*1024)
    int n = (int)(i >> 10);
    int k = (int)(i & 1023);
    const float* src;
    int r;
    if (n < 2048)       { src = Wf; r = n; }
    else if (n < 4096)  { src = Wq; r = n - 2048; }
    else if (n < 8192)  { r = (n - 4096) >> 1; src = (n & 1) ? Wv : Wi; }
    else                { r = (n - 8192) >> 1; src = (n & 1) ? Wg : Wup; }
    split_bf16(src[(size_t)r * 1024 + k], hi[i], lo[i]);
}

__global__ void conv_wout_kernel(const float* __restrict__ Wro, const float* __restrict__ Wd,
                                 __nv_bfloat16* __restrict__ hi, __nv_bfloat16* __restrict__ lo) {
    size_t i = (size_t)blockIdx.x * blockDim.x + threadIdx.x;     // [0, 1024*4096)
    int h = (int)(i >> 12);
    int j = (int)(i & 4095);
    float v = (j < 2048) ? Wro[(size_t)h * 2048 + j] : Wd[(size_t)h * 2048 + (j - 2048)];
    split_bf16(v, hi[i], lo[i]);
}

// ================= scan (two-level, chunked) =================
// P cols: f[0:2048)  q[2048:4096)  gc[4096:6144)
__global__ void scanA_kernel(const float* __restrict__ P,
                             float* __restrict__ Fc, float* __restrict__ Gc) {
    int r  = blockIdx.x * blockDim.x + threadIdx.x;
    int bc = blockIdx.y;
    int b = bc >> 6, ch = bc & 63;
    const float* row = P + (size_t)(b * SDIM + ch * CH) * PW;
    float F = 1.0f, G = 0.0f;
#pragma unroll 4
    for (int t = 0; t < CH; t++) {
        float f  = row[r];
        float gc = row[4096 + r];
        G = fmaf(f, G, gc);
        F *= f;
        row += PW;
    }
    Fc[(size_t)bc * RDIM + r] = F;
    Gc[(size_t)bc * RDIM + r] = G;
}

__global__ void scanB_kernel(const float* __restrict__ Fc, const float* __restrict__ Gc,
                             const float* __restrict__ init, float* __restrict__ Sc) {
    int i = blockIdx.x * blockDim.x + threadIdx.x;
    int b = i >> 11, r = i & 2047;
    float state = init[r];
    for (int ch = 0; ch < NCH; ch++) {
        size_t idx = (size_t)(b * NCH + ch) * RDIM + r;
        Sc[idx] = state;
        state = fmaf(Fc[idx], state, Gc[idx]);
    }
}

__global__ void scanC_kernel(const float* __restrict__ P, const float* __restrict__ Sc,
                             __nv_bfloat16* __restrict__ a2hi, __nv_bfloat16* __restrict__ a2lo) {
    int r  = blockIdx.x * blockDim.x + threadIdx.x;
    int bc = blockIdx.y;
    int b = bc >> 6, ch = bc & 63;
    int m0 = b * SDIM + ch * CH;
    const float* row = P + (size_t)m0 * PW;
    float state = Sc[(size_t)bc * RDIM + r];
#pragma unroll 4
    for (int t = 0; t < CH; t++) {
        float f  = row[r];
        float q  = row[2048 + r];
        float gc = row[4096 + r];
        state = fmaf(f, state, gc);
        float z = q * state;
        float ro = z / (1.0f + __expf(-z));
        __nv_bfloat16 hi, lo;
        split_bf16(ro, hi, lo);
        size_t oi = (size_t)(m0 + t) * KOUT + r;
        a2hi[oi] = hi;
        a2lo[oi] = lo;
        row += PW;
    }
}

// ================= launch =================
extern "C" void kernel_launch(void* const* d_in, const int* in_sizes, int n_in,
                              void* d_out, int out_size)
{
    const float* x    = (const float*)d_in[0];
    const float* Wf   = (const float*)d_in[1];
    const float* Wi   = (const float*)d_in[2];
    const float* Wv   = (const float*)d_in[3];
    const float* Wq   = (const float*)d_in[4];
    const float* Wro  = (const float*)d_in[5];
    const float* Wup  = (const float*)d_in[6];
    const float* Wg   = (const float*)d_in[7];
    const float* Wd   = (const float*)d_in[8];
    const float* init = (const float*)d_in[9];
    float* out = (float*)d_out;

    float *pP, *pFc, *pGc, *pSc;
    __nv_bfloat16 *pxhi, *pxlo, *pw6hi, *pw6lo, *pwohi, *pwolo, *pa2hi, *pa2lo;
    cudaGetSymbolAddress((void**)&pP,    g_P);
    cudaGetSymbolAddress((void**)&pxhi,  g_xhi);
    cudaGetSymbolAddress((void**)&pxlo,  g_xlo);
    cudaGetSymbolAddress((void**)&pw6hi, g_w6hi);
    cudaGetSymbolAddress((void**)&pw6lo, g_w6lo);
    cudaGetSymbolAddress((void**)&pwohi, g_wohi);
    cudaGetSymbolAddress((void**)&pwolo, g_wolo);
    cudaGetSymbolAddress((void**)&pa2hi, g_a2hi);
    cudaGetSymbolAddress((void**)&pa2lo, g_a2lo);
    cudaGetSymbolAddress((void**)&pFc,   g_Fc);
    cudaGetSymbolAddress((void**)&pGc,   g_Gc);
    cudaGetSymbolAddress((void**)&pSc,   g_Sc);

    // smem: GEMM1 (BM=64): (128+256)*80*2 = 61440 -> 3 CTAs/SM
    //       GEMM2 (BM=32): (64+256)*80*2  = 51200 -> 4 CTAs/SM
    const int SMEM1 = (2 * 64 + 256) * RSTR * 2;
    const int SMEM2 = (2 * 32 + 256) * RSTR * 2;
    cudaFuncSetAttribute((const void*)gemm_hmma<64, 4, 3>,
                         cudaFuncAttributeMaxDynamicSharedMemorySize, SMEM1);
    cudaFuncSetAttribute((const void*)gemm_hmma<32, 2, 4>,
                         cudaFuncAttributeMaxDynamicSharedMemorySize, SMEM2);

    // conversions
    conv_x_kernel   <<<(MDIM * HDIM) / 256, 256>>>(x, pxhi, pxlo);
    conv_w6_kernel  <<<(NPROJ * HDIM) / 256, 256>>>(Wf, Wi, Wv, Wq, Wup, Wg, pw6hi, pw6lo);
    conv_wout_kernel<<<(HDIM * KOUT) / 256, 256>>>(Wro, Wd, pwohi, pwolo);

    // GEMM1: regions f:tanh(1) q:none(0) gc:pair(4,4) h:pair(5,5) -> lut 0x554401
    {
        dim3 grid(NPROJ / BN, MDIM / 64);   // (96, 128)
        gemm_hmma<64, 4, 3><<<grid, 128, SMEM1>>>(pxhi, pxlo, pw6hi, pw6lo, HDIM,
                                                  pP, PW, pa2hi, pa2lo, 0x554401u);
    }

    // scan
    {
        dim3 gA(RDIM / 256, 4 * NCH);
        scanA_kernel<<<gA, 256>>>(pP, pFc, pGc);
        scanB_kernel<<<32, 256>>>(pFc, pGc, init, pSc);
        scanC_kernel<<<gA, 256>>>(pP, pSc, pa2hi, pa2lo);
    }

    // GEMM2: out = [ro | h] @ [Wro | Wd]^T   (act NONE everywhere)
    {
        dim3 grid(HDIM / BN, MDIM / 32);    // (8, 256)
        gemm_hmma<32, 2, 4><<<grid, 128, SMEM2>>>(pa2hi, pa2lo, pwohi, pwolo, KOUT,
                                                  out, HDIM, pa2hi, pa2lo, 0u);
    }
}

// round 9
// speedup vs baseline: 1.2884x; 1.2884x over previous
#include <cuda_runtime.h>
#include <cuda_fp16.h>
#include <stdint.h>
#include <math.h>

// ---------------- problem dims ----------------
#define MDIM 8192      // B*S
#define HDIM 1024
#define RDIM 2048
#define SDIM 2048
#define NPROJ 12288    // 6 * 2048 stacked projection outputs (GEMM1 N)
#define PW 6144        // P width after pair fusion: f | q | gc
#define KOUT 4096      // R + L for the output GEMM
#define NCH 64         // scan chunks
#define CH 32          // tokens per chunk

// ---------------- scratch (device globals) ----------------
__device__ float   g_P   [(size_t)MDIM * PW];              // f | q | gc
__device__ __half  g_xhi [(size_t)MDIM * HDIM];
__device__ __half  g_xlo [(size_t)MDIM * HDIM];
__device__ __half  g_w6hi[(size_t)NPROJ * HDIM];
__device__ __half  g_w6lo[(size_t)NPROJ * HDIM];
__device__ __half  g_wohi[(size_t)HDIM * KOUT];
__device__ __half  g_wolo[(size_t)HDIM * KOUT];
__device__ __half  g_a2  [(size_t)MDIM * KOUT];            // [ro | h], single fp16
__device__ float   g_Fc  [(size_t)4 * NCH * RDIM];
__device__ float   g_Gc  [(size_t)4 * NCH * RDIM];
__device__ float   g_Sc  [(size_t)4 * NCH * RDIM];

// ---------------- helpers ----------------
__device__ __forceinline__ uint32_t smem_u32(const void* p) {
    uint32_t a;
    asm("{ .reg .u64 t; cvta.to.shared.u64 t, %1; cvt.u32.u64 %0, t; }" : "=r"(a) : "l"(p));
    return a;
}
__device__ __forceinline__ void cp16(uint32_t s, const void* g) {
    asm volatile("cp.async.cg.shared.global [%0], [%1], 16;" :: "r"(s), "l"(g));
}
#define CP_COMMIT() asm volatile("cp.async.commit_group;" ::: "memory")
template<int N> __device__ __forceinline__ void cp_wait() {
    asm volatile("cp.async.wait_group %0;" :: "n"(N) : "memory");
}

__device__ __forceinline__ void ldm_x4(uint32_t (&d)[4], uint32_t a) {
    asm volatile("ldmatrix.sync.aligned.m8n8.x4.shared.b16 {%0,%1,%2,%3}, [%4];"
        : "=r"(d[0]), "=r"(d[1]), "=r"(d[2]), "=r"(d[3]) : "r"(a));
}
__device__ __forceinline__ void mma_f16(float (&c)[4], const uint32_t (&a)[4], const uint32_t* b) {
    asm volatile("mma.sync.aligned.m16n8k16.row.col.f32.f16.f16.f32 "
        "{%0,%1,%2,%3}, {%4,%5,%6,%7}, {%8,%9}, {%0,%1,%2,%3};"
        : "+f"(c[0]), "+f"(c[1]), "+f"(c[2]), "+f"(c[3])
        : "r"(a[0]), "r"(a[1]), "r"(a[2]), "r"(a[3]), "r"(b[0]), "r"(b[1]));
}

// ---------------- activations ----------------
// lut nibble: bits[0:2] act (0 none, 1 tanh, 4 gc-pair, 5 h-pair via values), bit3 = A-correction pass
#define ACT_NONE 0
#define ACT_TANH 1
#define ACT_GC 4     // pair: sigmoid(even) * silu(odd)   -> P (single col)
#define ACT_H  5     // pair: even * silu(odd)            -> a2 fp16

__device__ __forceinline__ float act_apply(float x, int act) {
    if (act == ACT_TANH) return tanhf(x);
    return x;
}
__device__ __forceinline__ float silu_f(float x) { return x / (1.0f + __expf(-x)); }
__device__ __forceinline__ float pair_act(float a, float b, int act) {
    if (act == ACT_GC) return (1.0f / (1.0f + __expf(-a))) * silu_f(b);
    return a * silu_f(b);   // ACT_H
}
__device__ __forceinline__ void split_fp16(float v, __half& hi, __half& lo) {
    hi = __float2half_rn(v);
    lo = __float2half_rn(v - __half2float(hi));
}

// ================= HMMA fp16 split GEMM =================
// C = act(A*B^T). B exact via Bhi+Blo fp16 (2 passes: Ahi*Bhi + Ahi*Blo).
// Regions with lut bit3 set add pass Alo*Bhi (A exact too; used for f).
// CTA BM_ x 128, 128 threads (4 warps), KC=32, 2-stage cp.async, OCC CTAs/SM.
#define BN 128
#define KC 32
#define RSTR 80         // 64B row + 16B pad (20-bank stride, conflict-free)

template<int BM_, int MI, int OCC>
__global__ void __launch_bounds__(128, OCC)
gemm_hmma(const __half* __restrict__ Ahi, const __half* __restrict__ Alo,
          const __half* __restrict__ Bhi, const __half* __restrict__ Blo,
          int K, float* __restrict__ C, int ldc,
          __half* __restrict__ aux, unsigned actlut)
{
    constexpr uint32_t OFF_AH = 0;
    constexpr uint32_t OFF_AL = BM_ * RSTR;
    constexpr uint32_t OFF_BH = 2 * BM_ * RSTR;
    constexpr uint32_t OFF_BL = (2 * BM_ + 128) * RSTR;
    constexpr uint32_t SB     = (2 * BM_ + 256) * RSTR;

    extern __shared__ char smem[];
    const uint32_t sbase = smem_u32(smem);
    const int tid  = threadIdx.x;
    const int bm   = blockIdx.y, bn = blockIdx.x;
    const int wn   = tid >> 5, lane = tid & 31;     // 4 warps in 1x4

    const int region = (bn * BN) >> 11;             // 2048-col region index
    const int nib    = (int)((actlut >> (region * 4)) & 15u);
    const int act    = nib & 7;
    const bool passA = (nib & 8) != 0;              // Alo*Bhi correction pass

    const __half* sA0 = Ahi + (size_t)bm * BM_ * K;
    const __half* sA1 = Alo + (size_t)bm * BM_ * K;
    const __half* sB0 = Bhi + (size_t)bn * BN * K;
    const __half* sB1 = Blo + (size_t)bn * BN * K;

    const int lcol  = tid & 3;          // 16B chunk within 64B row
    const int lrow0 = tid >> 2;         // 0..31

    auto load_stage = [&](int s) {
        const uint32_t sb = sbase + (uint32_t)(s & 1) * SB + lcol * 16;
        const int k0 = s * KC + lcol * 8;
#pragma unroll
        for (int i = 0; i < BM_ / 32; i++) {  // A hi (+lo if needed): BM_ rows
            int row = lrow0 + 32 * i;
            cp16(sb + OFF_AH + row * RSTR, sA0 + (size_t)row * K + k0);
            if (passA) cp16(sb + OFF_AL + row * RSTR, sA1 + (size_t)row * K + k0);
        }
#pragma unroll
        for (int i = 0; i < 4; i++) {         // B hi/lo: 128 rows each
            int row = lrow0 + 32 * i;
            cp16(sb + OFF_BH + row * RSTR, sB0 + (size_t)row * K + k0);
            cp16(sb + OFF_BL + row * RSTR, sB1 + (size_t)row * K + k0);
        }
    };

    // ldmatrix lane address geometry
    const int quad = lane >> 3, r8 = lane & 7;
    const uint32_t aoff = (uint32_t)((r8 + (quad & 1) * 8) * RSTR + (quad >> 1) * 16);
    const uint32_t boff = (uint32_t)((wn * 32 + r8 + (quad >> 1) * 8) * RSTR + (quad & 1) * 16);

    float acc[MI][4][4];
#pragma unroll
    for (int mi = 0; mi < MI; mi++)
#pragma unroll
        for (int nj = 0; nj < 4; nj++)
#pragma unroll
            for (int e = 0; e < 4; e++) acc[mi][nj][e] = 0.0f;

    const int ns = K / KC;
    load_stage(0); CP_COMMIT();

    for (int s = 0; s < ns; s++) {
        if (s + 1 < ns) load_stage(s + 1);
        CP_COMMIT();
        cp_wait<1>();
        __syncthreads();

        const uint32_t st = sbase + (uint32_t)(s & 1) * SB;
        const uint32_t aH = st + OFF_AH + aoff;
        const uint32_t aL = st + OFF_AL + aoff;
        const uint32_t bH = st + OFF_BH + boff;
        const uint32_t bL = st + OFF_BL + boff;

#pragma unroll
        for (int ks = 0; ks < 2; ks++) {
            const uint32_t kb = ks * 32;
            uint32_t afh[MI][4], bf[4][2];

            // A-hi fragments (MI x m16)
#pragma unroll
            for (int mi = 0; mi < MI; mi++) ldm_x4(afh[mi], aH + mi * (16 * RSTR) + kb);
            // B-hi fragments
#pragma unroll
            for (int t = 0; t < 2; t++) {
                uint32_t tt[4];
                ldm_x4(tt, bH + t * (16 * RSTR) + kb);
                bf[2 * t][0] = tt[0]; bf[2 * t][1] = tt[1];
                bf[2 * t + 1][0] = tt[2]; bf[2 * t + 1][1] = tt[3];
            }
            // pass 1: Ahi * Bhi
#pragma unroll
            for (int mi = 0; mi < MI; mi++)
#pragma unroll
                for (int nj = 0; nj < 4; nj++) mma_f16(acc[mi][nj], afh[mi], bf[nj]);
            // pass A-correction: Alo * Bhi (B-hi still live)
            if (passA) {
                uint32_t afl[MI][4];
#pragma unroll
                for (int mi = 0; mi < MI; mi++) ldm_x4(afl[mi], aL + mi * (16 * RSTR) + kb);
#pragma unroll
                for (int mi = 0; mi < MI; mi++)
#pragma unroll
                    for (int nj = 0; nj < 4; nj++) mma_f16(acc[mi][nj], afl[mi], bf[nj]);
            }
            // B-lo fragments (overwrite bf)
#pragma unroll
            for (int t = 0; t < 2; t++) {
                uint32_t tt[4];
                ldm_x4(tt, bL + t * (16 * RSTR) + kb);
                bf[2 * t][0] = tt[0]; bf[2 * t][1] = tt[1];
                bf[2 * t + 1][0] = tt[2]; bf[2 * t + 1][1] = tt[3];
            }
            // pass 2: Ahi * Blo
#pragma unroll
            for (int mi = 0; mi < MI; mi++)
#pragma unroll
                for (int nj = 0; nj < 4; nj++) mma_f16(acc[mi][nj], afh[mi], bf[nj]);
        }
        __syncthreads();
    }

    // ---- epilogue ----
    const int row0 = bm * BM_ + (lane >> 2);

    if (act < 4) {
        const int col0 = bn * BN + wn * 32 + 2 * (lane & 3);
#pragma unroll
        for (int mi = 0; mi < MI; mi++) {
#pragma unroll
            for (int nj = 0; nj < 4; nj++) {
                float2 v0, v1;
                v0.x = act_apply(acc[mi][nj][0], act);
                v0.y = act_apply(acc[mi][nj][1], act);
                v1.x = act_apply(acc[mi][nj][2], act);
                v1.y = act_apply(acc[mi][nj][3], act);
                size_t base = (size_t)(row0 + mi * 16) * ldc + col0 + nj * 8;
                *(float2*)(C + base)                   = v0;
                *(float2*)(C + base + (size_t)8 * ldc) = v1;
            }
        }
    } else {
        // pair regions: even/odd cols combined in-thread. Base from ACT, not
        // region (gc/h each span TWO 2048-regions).
        const int pcbase = ((bn * BN) >> 1) - ((act == ACT_GC) ? 2048 : 4096);
        const int pc0 = pcbase + wn * 16 + (lane & 3);
#pragma unroll
        for (int mi = 0; mi < MI; mi++) {
#pragma unroll
            for (int nj = 0; nj < 4; nj++) {
                float v0 = pair_act(acc[mi][nj][0], acc[mi][nj][1], act);
                float v1 = pair_act(acc[mi][nj][2], acc[mi][nj][3], act);
                int pc = pc0 + nj * 4;
                int r  = row0 + mi * 16;
                if (act == ACT_GC) {
                    C[(size_t)r * ldc + 4096 + pc]       = v0;  // gc at P cols 4096..6144
                    C[(size_t)(r + 8) * ldc + 4096 + pc] = v1;
                } else {
                    aux[(size_t)r * KOUT + 2048 + pc]       = __float2half_rn(v0);
                    aux[(size_t)(r + 8) * KOUT + 2048 + pc] = __float2half_rn(v1);
                }
            }
        }
    }
}

// ================= conversion kernels =================
__global__ void conv_x_kernel(const float* __restrict__ x,
                              __half* __restrict__ hi, __half* __restrict__ lo) {
    size_t i = (size_t)blockIdx.x * blockDim.x + threadIdx.x;
    split_fp16(x[i], hi[i], lo[i]);
}

// W6 stacking: [f(0:2048) | q(2048:4096) | g:c interleaved(4096:8192) | up:gate interleaved(8192:12288)]
__global__ void conv_w6_kernel(const float* __restrict__ Wf, const float* __restrict__ Wi,
                               const float* __restrict__ Wv, const float* __restrict__ Wq,
                               const float* __restrict__ Wup, const float* __restrict__ Wg,
                               __half* __restrict__ hi, __half* __restrict__ lo) {
    size_t i = (size_t)blockIdx.x * blockDim.x + threadIdx.x;     // [0, 12288*1024)
    int n = (int)(i >> 10);
    int k = (int)(i & 1023);
    const float* src;
    int r;
    if (n < 2048)       { src = Wf; r = n; }
    else if (n < 4096)  { src = Wq; r = n - 2048; }
    else if (n < 8192)  { r = (n - 4096) >> 1; src = (n & 1) ? Wv : Wi; }
    else                { r = (n - 8192) >> 1; src = (n & 1) ? Wg : Wup; }
    split_fp16(src[(size_t)r * 1024 + k], hi[i], lo[i]);
}

__global__ void conv_wout_kernel(const float* __restrict__ Wro, const float* __restrict__ Wd,
                                 __half* __restrict__ hi, __half* __restrict__ lo) {
    size_t i = (size_t)blockIdx.x * blockDim.x + threadIdx.x;     // [0, 1024*4096)
    int h = (int)(i >> 12);
    int j = (int)(i & 4095);
    float v = (j < 2048) ? Wro[(size_t)h * 2048 + j] : Wd[(size_t)h * 2048 + (j - 2048)];
    split_fp16(v, hi[i], lo[i]);
}

// ================= scan (two-level, chunked) =================
// P cols: f[0:2048)  q[2048:4096)  gc[4096:6144)
__global__ void scanA_kernel(const float* __restrict__ P,
                             float* __restrict__ Fc, float* __restrict__ Gc) {
    int r  = blockIdx.x * blockDim.x + threadIdx.x;
    int bc = blockIdx.y;
    int b = bc >> 6, ch = bc & 63;
    const float* row = P + (size_t)(b * SDIM + ch * CH) * PW;
    float F = 1.0f, G = 0.0f;
#pragma unroll 4
    for (int t = 0; t < CH; t++) {
        float f  = row[r];
        float gc = row[4096 + r];
        G = fmaf(f, G, gc);
        F *= f;
        row += PW;
    }
    Fc[(size_t)bc * RDIM + r] = F;
    Gc[(size_t)bc * RDIM + r] = G;
}

__global__ void scanB_kernel(const float* __restrict__ Fc, const float* __restrict__ Gc,
                             const float* __restrict__ init, float* __restrict__ Sc) {
    int i = blockIdx.x * blockDim.x + threadIdx.x;
    int b = i >> 11, r = i & 2047;
    float state = init[r];
    for (int ch = 0; ch < NCH; ch++) {
        size_t idx = (size_t)(b * NCH + ch) * RDIM + r;
        Sc[idx] = state;
        state = fmaf(Fc[idx], state, Gc[idx]);
    }
}

__global__ void scanC_kernel(const float* __restrict__ P, const float* __restrict__ Sc,
                             __half* __restrict__ a2) {
    int r  = blockIdx.x * blockDim.x + threadIdx.x;
    int bc = blockIdx.y;
    int b = bc >> 6, ch = bc & 63;
    int m0 = b * SDIM + ch * CH;
    const float* row = P + (size_t)m0 * PW;
    float state = Sc[(size_t)bc * RDIM + r];
#pragma unroll 4
    for (int t = 0; t < CH; t++) {
        float f  = row[r];
        float q  = row[2048 + r];
        float gc = row[4096 + r];
        state = fmaf(f, state, gc);
        float z = q * state;
        float ro = z / (1.0f + __expf(-z));
        a2[(size_t)(m0 + t) * KOUT + r] = __float2half_rn(ro);
        row += PW;
    }
}

// ================= launch =================
extern "C" void kernel_launch(void* const* d_in, const int* in_sizes, int n_in,
                              void* d_out, int out_size)
{
    const float* x    = (const float*)d_in[0];
    const float* Wf   = (const float*)d_in[1];
    const float* Wi   = (const float*)d_in[2];
    const float* Wv   = (const float*)d_in[3];
    const float* Wq   = (const float*)d_in[4];
    const float* Wro  = (const float*)d_in[5];
    const float* Wup  = (const float*)d_in[6];
    const float* Wg   = (const float*)d_in[7];
    const float* Wd   = (const float*)d_in[8];
    const float* init = (const float*)d_in[9];
    float* out = (float*)d_out;

    float *pP, *pFc, *pGc, *pSc;
    __half *pxhi, *pxlo, *pw6hi, *pw6lo, *pwohi, *pwolo, *pa2;
    cudaGetSymbolAddress((void**)&pP,    g_P);
    cudaGetSymbolAddress((void**)&pxhi,  g_xhi);
    cudaGetSymbolAddress((void**)&pxlo,  g_xlo);
    cudaGetSymbolAddress((void**)&pw6hi, g_w6hi);
    cudaGetSymbolAddress((void**)&pw6lo, g_w6lo);
    cudaGetSymbolAddress((void**)&pwohi, g_wohi);
    cudaGetSymbolAddress((void**)&pwolo, g_wolo);
    cudaGetSymbolAddress((void**)&pa2,   g_a2);
    cudaGetSymbolAddress((void**)&pFc,   g_Fc);
    cudaGetSymbolAddress((void**)&pGc,   g_Gc);
    cudaGetSymbolAddress((void**)&pSc,   g_Sc);

    // smem (BM=64): (128+256)*80*2 = 61440 -> 3 CTAs/SM
    const int SMEM1 = (2 * 64 + 256) * RSTR * 2;
    cudaFuncSetAttribute((const void*)gemm_hmma<64, 4, 3>,
                         cudaFuncAttributeMaxDynamicSharedMemorySize, SMEM1);

    // conversions
    conv_x_kernel   <<<(MDIM * HDIM) / 256, 256>>>(x, pxhi, pxlo);
    conv_w6_kernel  <<<(NPROJ * HDIM) / 256, 256>>>(Wf, Wi, Wv, Wq, Wup, Wg, pw6hi, pw6lo);
    conv_wout_kernel<<<(HDIM * KOUT) / 256, 256>>>(Wro, Wd, pwohi, pwolo);

    // GEMM1: regions f:tanh+Acorr(9) q:none(0) gc:pair(4,4) h:pair(5,5) -> lut 0x554409
    {
        dim3 grid(NPROJ / BN, MDIM / 64);   // (96, 128)
        gemm_hmma<64, 4, 3><<<grid, 128, SMEM1>>>(pxhi, pxlo, pw6hi, pw6lo, HDIM,
                                                  pP, PW, pa2, 0x554409u);
    }

    // scan
    {
        dim3 gA(RDIM / 256, 4 * NCH);
        scanA_kernel<<<gA, 256>>>(pP, pFc, pGc);
        scanB_kernel<<<32, 256>>>(pFc, pGc, init, pSc);
        scanC_kernel<<<gA, 256>>>(pP, pSc, pa2);
    }

    // GEMM2: out = [ro | h] @ [Wro | Wd]^T, A single fp16, 2-pass (lut 0)
    {
        dim3 grid(HDIM / BN, MDIM / 64);    // (8, 128)
        gemm_hmma<64, 4, 3><<<grid, 128, SMEM1>>>(pa2, pa2, pwohi, pwolo, KOUT,
                                                  out, HDIM, pa2, 0u);
    }
}

// round 10
// speedup vs baseline: 1.6675x; 1.2942x over previous
#include <cuda_runtime.h>
#include <cuda_fp16.h>
#include <stdint.h>
#include <math.h>

// ---------------- problem dims ----------------
#define MDIM 8192      // B*S
#define HDIM 1024
#define RDIM 2048
#define SDIM 2048
#define NPROJ 12288    // 6 * 2048 stacked projection outputs (GEMM1 N)
#define PW 6144        // P width after pair fusion: f | q | gc
#define KOUT 4096      // R + L for the output GEMM
#define NCH 64         // scan chunks
#define CH 32          // tokens per chunk

// ---------------- scratch (device globals) ----------------
__device__ float   g_P   [(size_t)MDIM * PW];              // f | q | gc
__device__ __half  g_xhi [(size_t)MDIM * HDIM];
__device__ __half  g_xlo [(size_t)MDIM * HDIM];
__device__ __half  g_w6hi[(size_t)NPROJ * HDIM];
__device__ __half  g_w6lo[(size_t)NPROJ * HDIM];
__device__ __half  g_wo  [(size_t)HDIM * KOUT];            // Wout single fp16
__device__ __half  g_a2  [(size_t)MDIM * KOUT];            // [ro | h], single fp16
__device__ float   g_Fc  [(size_t)4 * NCH * RDIM];
__device__ float   g_Gc  [(size_t)4 * NCH * RDIM];
__device__ float   g_Sc  [(size_t)4 * NCH * RDIM];

// ---------------- helpers ----------------
__device__ __forceinline__ uint32_t smem_u32(const void* p) {
    uint32_t a;
    asm("{ .reg .u64 t; cvta.to.shared.u64 t, %1; cvt.u32.u64 %0, t; }" : "=r"(a) : "l"(p));
    return a;
}
__device__ __forceinline__ void cp16(uint32_t s, const void* g) {
    asm volatile("cp.async.cg.shared.global [%0], [%1], 16;" :: "r"(s), "l"(g));
}
#define CP_COMMIT() asm volatile("cp.async.commit_group;" ::: "memory")
template<int N> __device__ __forceinline__ void cp_wait() {
    asm volatile("cp.async.wait_group %0;" :: "n"(N) : "memory");
}

__device__ __forceinline__ void ldm_x4(uint32_t (&d)[4], uint32_t a) {
    asm volatile("ldmatrix.sync.aligned.m8n8.x4.shared.b16 {%0,%1,%2,%3}, [%4];"
        : "=r"(d[0]), "=r"(d[1]), "=r"(d[2]), "=r"(d[3]) : "r"(a));
}
__device__ __forceinline__ void mma_f16(float (&c)[4], const uint32_t (&a)[4], const uint32_t* b) {
    asm volatile("mma.sync.aligned.m16n8k16.row.col.f32.f16.f16.f32 "
        "{%0,%1,%2,%3}, {%4,%5,%6,%7}, {%8,%9}, {%0,%1,%2,%3};"
        : "+f"(c[0]), "+f"(c[1]), "+f"(c[2]), "+f"(c[3])
        : "r"(a[0]), "r"(a[1]), "r"(a[2]), "r"(a[3]), "r"(b[0]), "r"(b[1]));
}

// ---------------- activations ----------------
// actlut nibble: bits[0:2] act (0 none, 1 tanh, 4 gc-pair, 5 h-pair), bit3 = Alo*Bhi pass
// blut: bit per 2048-col region = do Ahi*Blo pass
#define ACT_NONE 0
#define ACT_TANH 1
#define ACT_GC 4     // pair: sigmoid(even) * silu(odd)   -> P (single col)
#define ACT_H  5     // pair: even * silu(odd)            -> a2 fp16

__device__ __forceinline__ float act_apply(float x, int act) {
    if (act == ACT_TANH) return tanhf(x);
    return x;
}
__device__ __forceinline__ float silu_f(float x) { return x / (1.0f + __expf(-x)); }
__device__ __forceinline__ float pair_act(float a, float b, int act) {
    if (act == ACT_GC) return (1.0f / (1.0f + __expf(-a))) * silu_f(b);
    return a * silu_f(b);   // ACT_H
}
__device__ __forceinline__ void split_fp16(float v, __half& hi, __half& lo) {
    hi = __float2half_rn(v);
    lo = __float2half_rn(v - __half2float(hi));
}

// ================= HMMA fp16 variable-pass split GEMM =================
// C = act(A*B^T). Always Ahi*Bhi; +Alo*Bhi if actlut bit3; +Ahi*Blo if blut bit.
// Region pass plan (calibrated, each dropped pass ~1.5e-4 in quadrature):
//   f: 3-pass (recurrence-amplified), gc: 2-pass, q/h: 1-pass, GEMM2: 1-pass.
// CTA BM_ x 128, 128 threads (4 warps), KC=32, 2-stage cp.async, OCC CTAs/SM.
#define BN 128
#define KC 32
#define RSTR 80         // 64B row + 16B pad (20-bank stride, conflict-free)

template<int BM_, int MI, int OCC>
__global__ void __launch_bounds__(128, OCC)
gemm_hmma(const __half* __restrict__ Ahi, const __half* __restrict__ Alo,
          const __half* __restrict__ Bhi, const __half* __restrict__ Blo,
          int K, float* __restrict__ C, int ldc,
          __half* __restrict__ aux, unsigned actlut, unsigned blut)
{
    constexpr uint32_t OFF_AH = 0;
    constexpr uint32_t OFF_AL = BM_ * RSTR;
    constexpr uint32_t OFF_BH = 2 * BM_ * RSTR;
    constexpr uint32_t OFF_BL = (2 * BM_ + 128) * RSTR;
    constexpr uint32_t SB     = (2 * BM_ + 256) * RSTR;

    extern __shared__ char smem[];
    const uint32_t sbase = smem_u32(smem);
    const int tid  = threadIdx.x;
    const int bm   = blockIdx.y, bn = blockIdx.x;
    const int wn   = tid >> 5, lane = tid & 31;     // 4 warps in 1x4

    const int region = (bn * BN) >> 11;             // 2048-col region index
    const int nib    = (int)((actlut >> (region * 4)) & 15u);
    const int act    = nib & 7;
    const bool passA = (nib & 8) != 0;              // Alo*Bhi correction pass
    const bool passB = ((blut >> region) & 1u) != 0; // Ahi*Blo correction pass

    const __half* sA0 = Ahi + (size_t)bm * BM_ * K;
    const __half* sA1 = Alo + (size_t)bm * BM_ * K;
    const __half* sB0 = Bhi + (size_t)bn * BN * K;
    const __half* sB1 = Blo + (size_t)bn * BN * K;

    const int lcol  = tid & 3;          // 16B chunk within 64B row
    const int lrow0 = tid >> 2;         // 0..31

    auto load_stage = [&](int s) {
        const uint32_t sb = sbase + (uint32_t)(s & 1) * SB + lcol * 16;
        const int k0 = s * KC + lcol * 8;
#pragma unroll
        for (int i = 0; i < BM_ / 32; i++) {  // A hi (+lo if needed): BM_ rows
            int row = lrow0 + 32 * i;
            cp16(sb + OFF_AH + row * RSTR, sA0 + (size_t)row * K + k0);
            if (passA) cp16(sb + OFF_AL + row * RSTR, sA1 + (size_t)row * K + k0);
        }
#pragma unroll
        for (int i = 0; i < 4; i++) {         // B hi (+lo if needed): 128 rows
            int row = lrow0 + 32 * i;
            cp16(sb + OFF_BH + row * RSTR, sB0 + (size_t)row * K + k0);
            if (passB) cp16(sb + OFF_BL + row * RSTR, sB1 + (size_t)row * K + k0);
        }
    };

    // ldmatrix lane address geometry
    const int quad = lane >> 3, r8 = lane & 7;
    const uint32_t aoff = (uint32_t)((r8 + (quad & 1) * 8) * RSTR + (quad >> 1) * 16);
    const uint32_t boff = (uint32_t)((wn * 32 + r8 + (quad >> 1) * 8) * RSTR + (quad & 1) * 16);

    float acc[MI][4][4];
#pragma unroll
    for (int mi = 0; mi < MI; mi++)
#pragma unroll
        for (int nj = 0; nj < 4; nj++)
#pragma unroll
            for (int e = 0; e < 4; e++) acc[mi][nj][e] = 0.0f;

    const int ns = K / KC;
    load_stage(0); CP_COMMIT();

    for (int s = 0; s < ns; s++) {
        if (s + 1 < ns) load_stage(s + 1);
        CP_COMMIT();
        cp_wait<1>();
        __syncthreads();

        const uint32_t st = sbase + (uint32_t)(s & 1) * SB;
        const uint32_t aH = st + OFF_AH + aoff;
        const uint32_t aL = st + OFF_AL + aoff;
        const uint32_t bH = st + OFF_BH + boff;
        const uint32_t bL = st + OFF_BL + boff;

#pragma unroll
        for (int ks = 0; ks < 2; ks++) {
            const uint32_t kb = ks * 32;
            uint32_t afh[MI][4], bf[4][2];

            // A-hi fragments (MI x m16)
#pragma unroll
            for (int mi = 0; mi < MI; mi++) ldm_x4(afh[mi], aH + mi * (16 * RSTR) + kb);
            // B-hi fragments
#pragma unroll
            for (int t = 0; t < 2; t++) {
                uint32_t tt[4];
                ldm_x4(tt, bH + t * (16 * RSTR) + kb);
                bf[2 * t][0] = tt[0]; bf[2 * t][1] = tt[1];
                bf[2 * t + 1][0] = tt[2]; bf[2 * t + 1][1] = tt[3];
            }
            // pass 1: Ahi * Bhi
#pragma unroll
            for (int mi = 0; mi < MI; mi++)
#pragma unroll
                for (int nj = 0; nj < 4; nj++) mma_f16(acc[mi][nj], afh[mi], bf[nj]);
            // optional: Alo * Bhi (B-hi still live)
            if (passA) {
                uint32_t afl[MI][4];
#pragma unroll
                for (int mi = 0; mi < MI; mi++) ldm_x4(afl[mi], aL + mi * (16 * RSTR) + kb);
#pragma unroll
                for (int mi = 0; mi < MI; mi++)
#pragma unroll
                    for (int nj = 0; nj < 4; nj++) mma_f16(acc[mi][nj], afl[mi], bf[nj]);
            }
            // optional: Ahi * Blo
            if (passB) {
#pragma unroll
                for (int t = 0; t < 2; t++) {
                    uint32_t tt[4];
                    ldm_x4(tt, bL + t * (16 * RSTR) + kb);
                    bf[2 * t][0] = tt[0]; bf[2 * t][1] = tt[1];
                    bf[2 * t + 1][0] = tt[2]; bf[2 * t + 1][1] = tt[3];
                }
#pragma unroll
                for (int mi = 0; mi < MI; mi++)
#pragma unroll
                    for (int nj = 0; nj < 4; nj++) mma_f16(acc[mi][nj], afh[mi], bf[nj]);
            }
        }
        __syncthreads();
    }

    // ---- epilogue ----
    const int row0 = bm * BM_ + (lane >> 2);

    if (act < 4) {
        const int col0 = bn * BN + wn * 32 + 2 * (lane & 3);
#pragma unroll
        for (int mi = 0; mi < MI; mi++) {
#pragma unroll
            for (int nj = 0; nj < 4; nj++) {
                float2 v0, v1;
                v0.x = act_apply(acc[mi][nj][0], act);
                v0.y = act_apply(acc[mi][nj][1], act);
                v1.x = act_apply(acc[mi][nj][2], act);
                v1.y = act_apply(acc[mi][nj][3], act);
                size_t base = (size_t)(row0 + mi * 16) * ldc + col0 + nj * 8;
                *(float2*)(C + base)                   = v0;
                *(float2*)(C + base + (size_t)8 * ldc) = v1;
            }
        }
    } else {
        // pair regions: even/odd cols combined in-thread. Base from ACT, not
        // region (gc/h each span TWO 2048-regions).
        const int pcbase = ((bn * BN) >> 1) - ((act == ACT_GC) ? 2048 : 4096);
        const int pc0 = pcbase + wn * 16 + (lane & 3);
#pragma unroll
        for (int mi = 0; mi < MI; mi++) {
#pragma unroll
            for (int nj = 0; nj < 4; nj++) {
                float v0 = pair_act(acc[mi][nj][0], acc[mi][nj][1], act);
                float v1 = pair_act(acc[mi][nj][2], acc[mi][nj][3], act);
                int pc = pc0 + nj * 4;
                int r  = row0 + mi * 16;
                if (act == ACT_GC) {
                    C[(size_t)r * ldc + 4096 + pc]       = v0;  // gc at P cols 4096..6144
                    C[(size_t)(r + 8) * ldc + 4096 + pc] = v1;
                } else {
                    aux[(size_t)r * KOUT + 2048 + pc]       = __float2half_rn(v0);
                    aux[(size_t)(r + 8) * KOUT + 2048 + pc] = __float2half_rn(v1);
                }
            }
        }
    }
}

// ================= conversion kernels =================
__global__ void conv_x_kernel(const float* __restrict__ x,
                              __half* __restrict__ hi, __half* __restrict__ lo) {
    size_t i = (size_t)blockIdx.x * blockDim.x + threadIdx.x;
    split_fp16(x[i], hi[i], lo[i]);
}

// W6 stacking: [f(0:2048) | q(2048:4096) | g:c interleaved(4096:8192) | up:gate interleaved(8192:12288)]
__global__ void conv_w6_kernel(const float* __restrict__ Wf, const float* __restrict__ Wi,
                               const float* __restrict__ Wv, const float* __restrict__ Wq,
                               const float* __restrict__ Wup, const float* __restrict__ Wg,
                               __half* __restrict__ hi, __half* __restrict__ lo) {
    size_t i = (size_t)blockIdx.x * blockDim.x + threadIdx.x;     // [0, 12288*1024)
    int n = (int)(i >> 10);
    int k = (int)(i & 1023);
    const float* src;
    int r;
    if (n < 2048)       { src = Wf; r = n; }
    else if (n < 4096)  { src = Wq; r = n - 2048; }
    else if (n < 8192)  { r = (n - 4096) >> 1; src = (n & 1) ? Wv : Wi; }
    else                { r = (n - 8192) >> 1; src = (n & 1) ? Wg : Wup; }
    split_fp16(src[(size_t)r * 1024 + k], hi[i], lo[i]);
}

__global__ void conv_wout_kernel(const float* __restrict__ Wro, const float* __restrict__ Wd,
                                 __half* __restrict__ w) {
    size_t i = (size_t)blockIdx.x * blockDim.x + threadIdx.x;     // [0, 1024*4096)
    int h = (int)(i >> 12);
    int j = (int)(i & 4095);
    float v = (j < 2048) ? Wro[(size_t)h * 2048 + j] : Wd[(size_t)h * 2048 + (j - 2048)];
    w[i] = __float2half_rn(v);
}

// ================= scan (two-level, chunked) =================
// P cols: f[0:2048)  q[2048:4096)  gc[4096:6144)
__global__ void scanA_kernel(const float* __restrict__ P,
                             float* __restrict__ Fc, float* __restrict__ Gc) {
    int r  = blockIdx.x * blockDim.x + threadIdx.x;
    int bc = blockIdx.y;
    int b = bc >> 6, ch = bc & 63;
    const float* row = P + (size_t)(b * SDIM + ch * CH) * PW;
    float F = 1.0f, G = 0.0f;
#pragma unroll 4
    for (int t = 0; t < CH; t++) {
        float f  = row[r];
        float gc = row[4096 + r];
        G = fmaf(f, G, gc);
        F *= f;
        row += PW;
    }
    Fc[(size_t)bc * RDIM + r] = F;
    Gc[(size_t)bc * RDIM + r] = G;
}

__global__ void scanB_kernel(const float* __restrict__ Fc, const float* __restrict__ Gc,
                             const float* __restrict__ init, float* __restrict__ Sc) {
    int i = blockIdx.x * blockDim.x + threadIdx.x;
    int b = i >> 11, r = i & 2047;
    float state = init[r];
    for (int ch = 0; ch < NCH; ch++) {
        size_t idx = (size_t)(b * NCH + ch) * RDIM + r;
        Sc[idx] = state;
        state = fmaf(Fc[idx], state, Gc[idx]);
    }
}

__global__ void scanC_kernel(const float* __restrict__ P, const float* __restrict__ Sc,
                             __half* __restrict__ a2) {
    int r  = blockIdx.x * blockDim.x + threadIdx.x;
    int bc = blockIdx.y;
    int b = bc >> 6, ch = bc & 63;
    int m0 = b * SDIM + ch * CH;
    const float* row = P + (size_t)m0 * PW;
    float state = Sc[(size_t)bc * RDIM + r];
#pragma unroll 4
    for (int t = 0; t < CH; t++) {
        float f  = row[r];
        float q  = row[2048 + r];
        float gc = row[4096 + r];
        state = fmaf(f, state, gc);
        float z = q * state;
        float ro = z / (1.0f + __expf(-z));
        a2[(size_t)(m0 + t) * KOUT + r] = __float2half_rn(ro);
        row += PW;
    }
}

// ================= launch =================
extern "C" void kernel_launch(void* const* d_in, const int* in_sizes, int n_in,
                              void* d_out, int out_size)
{
    const float* x    = (const float*)d_in[0];
    const float* Wf   = (const float*)d_in[1];
    const float* Wi   = (const float*)d_in[2];
    const float* Wv   = (const float*)d_in[3];
    const float* Wq   = (const float*)d_in[4];
    const float* Wro  = (const float*)d_in[5];
    const float* Wup  = (const float*)d_in[6];
    const float* Wg   = (const float*)d_in[7];
    const float* Wd   = (const float*)d_in[8];
    const float* init = (const float*)d_in[9];
    float* out = (float*)d_out;

    float *pP, *pFc, *pGc, *pSc;
    __half *pxhi, *pxlo, *pw6hi, *pw6lo, *pwo, *pa2;
    cudaGetSymbolAddress((void**)&pP,    g_P);
    cudaGetSymbolAddress((void**)&pxhi,  g_xhi);
    cudaGetSymbolAddress((void**)&pxlo,  g_xlo);
    cudaGetSymbolAddress((void**)&pw6hi, g_w6hi);
    cudaGetSymbolAddress((void**)&pw6lo, g_w6lo);
    cudaGetSymbolAddress((void**)&pwo,   g_wo);
    cudaGetSymbolAddress((void**)&pa2,   g_a2);
    cudaGetSymbolAddress((void**)&pFc,   g_Fc);
    cudaGetSymbolAddress((void**)&pGc,   g_Gc);
    cudaGetSymbolAddress((void**)&pSc,   g_Sc);

    // smem (BM=64): (128+256)*80*2 = 61440 -> 3 CTAs/SM
    const int SMEM1 = (2 * 64 + 256) * RSTR * 2;
    cudaFuncSetAttribute((const void*)gemm_hmma<64, 4, 3>,
                         cudaFuncAttributeMaxDynamicSharedMemorySize, SMEM1);

    // conversions
    conv_x_kernel   <<<(MDIM * HDIM) / 256, 256>>>(x, pxhi, pxlo);
    conv_w6_kernel  <<<(NPROJ * HDIM) / 256, 256>>>(Wf, Wi, Wv, Wq, Wup, Wg, pw6hi, pw6lo);
    conv_wout_kernel<<<(HDIM * KOUT) / 256, 256>>>(Wro, Wd, pwo);

    // GEMM1 pass plan: f 3-pass (act=tanh, A+B corr), q 1-pass, gc 2-pass
    // (B corr), h 1-pass. actlut nibbles: f=9 q=0 gc=4,4 h=5,5 -> 0x554409.
    // blut: Blo pass for regions {0 (f), 2,3 (gc)} -> 0b001101 = 0x0D.
    {
        dim3 grid(NPROJ / BN, MDIM / 64);   // (96, 128)
        gemm_hmma<64, 4, 3><<<grid, 128, SMEM1>>>(pxhi, pxlo, pw6hi, pw6lo, HDIM,
                                                  pP, PW, pa2, 0x554409u, 0x0Du);
    }

    // scan
    {
        dim3 gA(RDIM / 256, 4 * NCH);
        scanA_kernel<<<gA, 256>>>(pP, pFc, pGc);
        scanB_kernel<<<32, 256>>>(pFc, pGc, init, pSc);
        scanC_kernel<<<gA, 256>>>(pP, pSc, pa2);
    }

    // GEMM2: out = [ro | h] @ Wout^T, single-pass fp16 both sides
    {
        dim3 grid(HDIM / BN, MDIM / 64);    // (8, 128)
        gemm_hmma<64, 4, 3><<<grid, 128, SMEM1>>>(pa2, pa2, pwo, pwo, KOUT,
                                                  out, HDIM, pa2, 0u, 0u);
    }
}

// round 11
// speedup vs baseline: 1.8878x; 1.1321x over previous
#include <cuda_runtime.h>
#include <cuda_fp16.h>
#include <stdint.h>
#include <math.h>

// ---------------- problem dims ----------------
#define MDIM 8192      // B*S
#define HDIM 1024
#define RDIM 2048
#define SDIM 2048
#define NPROJ 12288    // 6 * 2048 stacked projection outputs (GEMM1 N)
#define PW 6144        // P width after pair fusion: f | q | gc
#define KOUT 4096      // R + L for the output GEMM
#define NCH 64         // scan chunks
#define CH 32          // tokens per chunk

// ---------------- scratch (device globals) ----------------
__device__ float   g_P   [(size_t)MDIM * PW];              // f | q | gc
__device__ __half  g_xhi [(size_t)MDIM * HDIM];
__device__ __half  g_xlo [(size_t)MDIM * HDIM];
__device__ __half  g_w6hi[(size_t)NPROJ * HDIM];
__device__ __half  g_w6lo[(size_t)NPROJ * HDIM];
__device__ __half  g_wo  [(size_t)HDIM * KOUT];            // Wout single fp16
__device__ __half  g_a2  [(size_t)MDIM * KOUT];            // [ro | h], single fp16
__device__ float   g_Fc  [(size_t)4 * NCH * RDIM];
__device__ float   g_Gc  [(size_t)4 * NCH * RDIM];
__device__ float   g_Sc  [(size_t)4 * NCH * RDIM];

// ---------------- helpers ----------------
__device__ __forceinline__ uint32_t smem_u32(const void* p) {
    uint32_t a;
    asm("{ .reg .u64 t; cvta.to.shared.u64 t, %1; cvt.u32.u64 %0, t; }" : "=r"(a) : "l"(p));
    return a;
}
__device__ __forceinline__ void cp16(uint32_t s, const void* g) {
    asm volatile("cp.async.cg.shared.global [%0], [%1], 16;" :: "r"(s), "l"(g));
}
#define CP_COMMIT() asm volatile("cp.async.commit_group;" ::: "memory")
template<int N> __device__ __forceinline__ void cp_wait() {
    asm volatile("cp.async.wait_group %0;" :: "n"(N) : "memory");
}

__device__ __forceinline__ void ldm_x4(uint32_t (&d)[4], uint32_t a) {
    asm volatile("ldmatrix.sync.aligned.m8n8.x4.shared.b16 {%0,%1,%2,%3}, [%4];"
        : "=r"(d[0]), "=r"(d[1]), "=r"(d[2]), "=r"(d[3]) : "r"(a));
}
__device__ __forceinline__ void mma_f16(float (&c)[4], const uint32_t (&a)[4], const uint32_t* b) {
    asm volatile("mma.sync.aligned.m16n8k16.row.col.f32.f16.f16.f32 "
        "{%0,%1,%2,%3}, {%4,%5,%6,%7}, {%8,%9}, {%0,%1,%2,%3};"
        : "+f"(c[0]), "+f"(c[1]), "+f"(c[2]), "+f"(c[3])
        : "r"(a[0]), "r"(a[1]), "r"(a[2]), "r"(a[3]), "r"(b[0]), "r"(b[1]));
}

// ---------------- activations ----------------
// actlut nibble: bits[0:2] act (0 none, 1 tanh, 4 gc-pair, 5 h-pair), bit3 = Alo*Bhi pass
// blut: bit per 2048-col region = do Ahi*Blo pass
#define ACT_NONE 0
#define ACT_TANH 1
#define ACT_GC 4     // pair: sigmoid(even) * silu(odd)   -> P (single col)
#define ACT_H  5     // pair: even * silu(odd)            -> a2 fp16

__device__ __forceinline__ float act_apply(float x, int act) {
    if (act == ACT_TANH) return tanhf(x);
    return x;
}
__device__ __forceinline__ float silu_f(float x) { return x / (1.0f + __expf(-x)); }
__device__ __forceinline__ float pair_act(float a, float b, int act) {
    if (act == ACT_GC) return (1.0f / (1.0f + __expf(-a))) * silu_f(b);
    return a * silu_f(b);   // ACT_H
}
__device__ __forceinline__ void split_fp16(float v, __half& hi, __half& lo) {
    hi = __float2half_rn(v);
    lo = __float2half_rn(v - __half2float(hi));
}

// ================= HMMA fp16 variable-pass split GEMM =================
// C = act(A*B^T). Always Ahi*Bhi; +Alo*Bhi if actlut bit3; +Ahi*Blo if blut bit.
// Region pass plan (calibrated: each dropped pass ~1.5e-4, quadrature):
//   f: 3-pass (recurrence-amplified), q/gc/h: 1-pass, GEMM2: 1-pass.
// CTA BM_ x 128, 128 threads (4 warps), KC=32, 2-stage cp.async, OCC CTAs/SM.
#define BN 128
#define KC 32
#define RSTR 80         // 64B row + 16B pad (20-bank stride, conflict-free)

template<int BM_, int MI, int OCC>
__global__ void __launch_bounds__(128, OCC)
gemm_hmma(const __half* __restrict__ Ahi, const __half* __restrict__ Alo,
          const __half* __restrict__ Bhi, const __half* __restrict__ Blo,
          int K, float* __restrict__ C, int ldc,
          __half* __restrict__ aux, unsigned actlut, unsigned blut)
{
    constexpr uint32_t OFF_AH = 0;
    constexpr uint32_t OFF_AL = BM_ * RSTR;
    constexpr uint32_t OFF_BH = 2 * BM_ * RSTR;
    constexpr uint32_t OFF_BL = (2 * BM_ + 128) * RSTR;
    constexpr uint32_t SB     = (2 * BM_ + 256) * RSTR;

    extern __shared__ char smem[];
    const uint32_t sbase = smem_u32(smem);
    const int tid  = threadIdx.x;
    const int bm   = blockIdx.y, bn = blockIdx.x;
    const int wn   = tid >> 5, lane = tid & 31;     // 4 warps in 1x4

    const int region = (bn * BN) >> 11;             // 2048-col region index
    const int nib    = (int)((actlut >> (region * 4)) & 15u);
    const int act    = nib & 7;
    const bool passA = (nib & 8) != 0;              // Alo*Bhi correction pass
    const bool passB = ((blut >> region) & 1u) != 0; // Ahi*Blo correction pass

    const __half* sA0 = Ahi + (size_t)bm * BM_ * K;
    const __half* sA1 = Alo + (size_t)bm * BM_ * K;
    const __half* sB0 = Bhi + (size_t)bn * BN * K;
    const __half* sB1 = Blo + (size_t)bn * BN * K;

    const int lcol  = tid & 3;          // 16B chunk within 64B row
    const int lrow0 = tid >> 2;         // 0..31

    auto load_stage = [&](int s) {
        const uint32_t sb = sbase + (uint32_t)(s & 1) * SB + lcol * 16;
        const int k0 = s * KC + lcol * 8;
#pragma unroll
        for (int i = 0; i < BM_ / 32; i++) {  // A hi (+lo if needed): BM_ rows
            int row = lrow0 + 32 * i;
            cp16(sb + OFF_AH + row * RSTR, sA0 + (size_t)row * K + k0);
            if (passA) cp16(sb + OFF_AL + row * RSTR, sA1 + (size_t)row * K + k0);
        }
#pragma unroll
        for (int i = 0; i < 4; i++) {         // B hi (+lo if needed): 128 rows
            int row = lrow0 + 32 * i;
            cp16(sb + OFF_BH + row * RSTR, sB0 + (size_t)row * K + k0);
            if (passB) cp16(sb + OFF_BL + row * RSTR, sB1 + (size_t)row * K + k0);
        }
    };

    // ldmatrix lane address geometry
    const int quad = lane >> 3, r8 = lane & 7;
    const uint32_t aoff = (uint32_t)((r8 + (quad & 1) * 8) * RSTR + (quad >> 1) * 16);
    const uint32_t boff = (uint32_t)((wn * 32 + r8 + (quad >> 1) * 8) * RSTR + (quad & 1) * 16);

    float acc[MI][4][4];
#pragma unroll
    for (int mi = 0; mi < MI; mi++)
#pragma unroll
        for (int nj = 0; nj < 4; nj++)
#pragma unroll
            for (int e = 0; e < 4; e++) acc[mi][nj][e] = 0.0f;

    const int ns = K / KC;
    load_stage(0); CP_COMMIT();

    for (int s = 0; s < ns; s++) {
        if (s + 1 < ns) load_stage(s + 1);
        CP_COMMIT();
        cp_wait<1>();
        __syncthreads();

        const uint32_t st = sbase + (uint32_t)(s & 1) * SB;
        const uint32_t aH = st + OFF_AH + aoff;
        const uint32_t aL = st + OFF_AL + aoff;
        const uint32_t bH = st + OFF_BH + boff;
        const uint32_t bL = st + OFF_BL + boff;

#pragma unroll
        for (int ks = 0; ks < 2; ks++) {
            const uint32_t kb = ks * 32;
            uint32_t afh[MI][4], bf[4][2];

            // A-hi fragments (MI x m16)
#pragma unroll
            for (int mi = 0; mi < MI; mi++) ldm_x4(afh[mi], aH + mi * (16 * RSTR) + kb);
            // B-hi fragments
#pragma unroll
            for (int t = 0; t < 2; t++) {
                uint32_t tt[4];
                ldm_x4(tt, bH + t * (16 * RSTR) + kb);
                bf[2 * t][0] = tt[0]; bf[2 * t][1] = tt[1];
                bf[2 * t + 1][0] = tt[2]; bf[2 * t + 1][1] = tt[3];
            }
            // pass 1: Ahi * Bhi
#pragma unroll
            for (int mi = 0; mi < MI; mi++)
#pragma unroll
                for (int nj = 0; nj < 4; nj++) mma_f16(acc[mi][nj], afh[mi], bf[nj]);
            // optional: Alo * Bhi (B-hi still live)
            if (passA) {
                uint32_t afl[MI][4];
#pragma unroll
                for (int mi = 0; mi < MI; mi++) ldm_x4(afl[mi], aL + mi * (16 * RSTR) + kb);
#pragma unroll
                for (int mi = 0; mi < MI; mi++)
#pragma unroll
                    for (int nj = 0; nj < 4; nj++) mma_f16(acc[mi][nj], afl[mi], bf[nj]);
            }
            // optional: Ahi * Blo
            if (passB) {
#pragma unroll
                for (int t = 0; t < 2; t++) {
                    uint32_t tt[4];
                    ldm_x4(tt, bL + t * (16 * RSTR) + kb);
                    bf[2 * t][0] = tt[0]; bf[2 * t][1] = tt[1];
                    bf[2 * t + 1][0] = tt[2]; bf[2 * t + 1][1] = tt[3];
                }
#pragma unroll
                for (int mi = 0; mi < MI; mi++)
#pragma unroll
                    for (int nj = 0; nj < 4; nj++) mma_f16(acc[mi][nj], afh[mi], bf[nj]);
            }
        }
        __syncthreads();
    }

    // ---- epilogue ----
    const int row0 = bm * BM_ + (lane >> 2);

    if (act < 4) {
        const int col0 = bn * BN + wn * 32 + 2 * (lane & 3);
#pragma unroll
        for (int mi = 0; mi < MI; mi++) {
#pragma unroll
            for (int nj = 0; nj < 4; nj++) {
                float2 v0, v1;
                v0.x = act_apply(acc[mi][nj][0], act);
                v0.y = act_apply(acc[mi][nj][1], act);
                v1.x = act_apply(acc[mi][nj][2], act);
                v1.y = act_apply(acc[mi][nj][3], act);
                size_t base = (size_t)(row0 + mi * 16) * ldc + col0 + nj * 8;
                *(float2*)(C + base)                   = v0;
                *(float2*)(C + base + (size_t)8 * ldc) = v1;
            }
        }
    } else {
        // pair regions: even/odd cols combined in-thread. Base from ACT, not
        // region (gc/h each span TWO 2048-regions).
        const int pcbase = ((bn * BN) >> 1) - ((act == ACT_GC) ? 2048 : 4096);
        const int pc0 = pcbase + wn * 16 + (lane & 3);
#pragma unroll
        for (int mi = 0; mi < MI; mi++) {
#pragma unroll
            for (int nj = 0; nj < 4; nj++) {
                float v0 = pair_act(acc[mi][nj][0], acc[mi][nj][1], act);
                float v1 = pair_act(acc[mi][nj][2], acc[mi][nj][3], act);
                int pc = pc0 + nj * 4;
                int r  = row0 + mi * 16;
                if (act == ACT_GC) {
                    C[(size_t)r * ldc + 4096 + pc]       = v0;  // gc at P cols 4096..6144
                    C[(size_t)(r + 8) * ldc + 4096 + pc] = v1;
                } else {
                    aux[(size_t)r * KOUT + 2048 + pc]       = __float2half_rn(v0);
                    aux[(size_t)(r + 8) * KOUT + 2048 + pc] = __float2half_rn(v1);
                }
            }
        }
    }
}

// ================= conversion kernels =================
__global__ void conv_x_kernel(const float* __restrict__ x,
                              __half* __restrict__ hi, __half* __restrict__ lo) {
    size_t i = (size_t)blockIdx.x * blockDim.x + threadIdx.x;
    split_fp16(x[i], hi[i], lo[i]);
}

// W6 stacking: [f(0:2048) | q(2048:4096) | g:c interleaved(4096:8192) | up:gate interleaved(8192:12288)]
__global__ void conv_w6_kernel(const float* __restrict__ Wf, const float* __restrict__ Wi,
                               const float* __restrict__ Wv, const float* __restrict__ Wq,
                               const float* __restrict__ Wup, const float* __restrict__ Wg,
                               __half* __restrict__ hi, __half* __restrict__ lo) {
    size_t i = (size_t)blockIdx.x * blockDim.x + threadIdx.x;     // [0, 12288*1024)
    int n = (int)(i >> 10);
    int k = (int)(i & 1023);
    const float* src;
    int r;
    if (n < 2048)       { src = Wf; r = n; }
    else if (n < 4096)  { src = Wq; r = n - 2048; }
    else if (n < 8192)  { r = (n - 4096) >> 1; src = (n & 1) ? Wv : Wi; }
    else                { r = (n - 8192) >> 1; src = (n & 1) ? Wg : Wup; }
    split_fp16(src[(size_t)r * 1024 + k], hi[i], lo[i]);
}

__global__ void conv_wout_kernel(const float* __restrict__ Wro, const float* __restrict__ Wd,
                                 __half* __restrict__ w) {
    size_t i = (size_t)blockIdx.x * blockDim.x + threadIdx.x;     // [0, 1024*4096)
    int h = (int)(i >> 12);
    int j = (int)(i & 4095);
    float v = (j < 2048) ? Wro[(size_t)h * 2048 + j] : Wd[(size_t)h * 2048 + (j - 2048)];
    w[i] = __float2half_rn(v);
}

// ================= scan (two-level, chunked) =================
// P cols: f[0:2048)  q[2048:4096)  gc[4096:6144)
__global__ void scanA_kernel(const float* __restrict__ P,
                             float* __restrict__ Fc, float* __restrict__ Gc) {
    int r  = blockIdx.x * blockDim.x + threadIdx.x;
    int bc = blockIdx.y;
    int b = bc >> 6, ch = bc & 63;
    const float* row = P + (size_t)(b * SDIM + ch * CH) * PW;
    float F = 1.0f, G = 0.0f;
#pragma unroll 4
    for (int t = 0; t < CH; t++) {
        float f  = row[r];
        float gc = row[4096 + r];
        G = fmaf(f, G, gc);
        F *= f;
        row += PW;
    }
    Fc[(size_t)bc * RDIM + r] = F;
    Gc[(size_t)bc * RDIM + r] = G;
}

__global__ void scanB_kernel(const float* __restrict__ Fc, const float* __restrict__ Gc,
                             const float* __restrict__ init, float* __restrict__ Sc) {
    int i = blockIdx.x * blockDim.x + threadIdx.x;
    int b = i >> 11, r = i & 2047;
    float state = init[r];
    for (int ch = 0; ch < NCH; ch++) {
        size_t idx = (size_t)(b * NCH + ch) * RDIM + r;
        Sc[idx] = state;
        state = fmaf(Fc[idx], state, Gc[idx]);
    }
}

__global__ void scanC_kernel(const float* __restrict__ P, const float* __restrict__ Sc,
                             __half* __restrict__ a2) {
    int r  = blockIdx.x * blockDim.x + threadIdx.x;
    int bc = blockIdx.y;
    int b = bc >> 6, ch = bc & 63;
    int m0 = b * SDIM + ch * CH;
    const float* row = P + (size_t)m0 * PW;
    float state = Sc[(size_t)bc * RDIM + r];
#pragma unroll 4
    for (int t = 0; t < CH; t++) {
        float f  = row[r];
        float q  = row[2048 + r];
        float gc = row[4096 + r];
        state = fmaf(f, state, gc);
        float z = q * state;
        float ro = z / (1.0f + __expf(-z));
        a2[(size_t)(m0 + t) * KOUT + r] = __float2half_rn(ro);
        row += PW;
    }
}

// ================= launch =================
extern "C" void kernel_launch(void* const* d_in, const int* in_sizes, int n_in,
                              void* d_out, int out_size)
{
    const float* x    = (const float*)d_in[0];
    const float* Wf   = (const float*)d_in[1];
    const float* Wi   = (const float*)d_in[2];
    const float* Wv   = (const float*)d_in[3];
    const float* Wq   = (const float*)d_in[4];
    const float* Wro  = (const float*)d_in[5];
    const float* Wup  = (const float*)d_in[6];
    const float* Wg   = (const float*)d_in[7];
    const float* Wd   = (const float*)d_in[8];
    const float* init = (const float*)d_in[9];
    float* out = (float*)d_out;

    float *pP, *pFc, *pGc, *pSc;
    __half *pxhi, *pxlo, *pw6hi, *pw6lo, *pwo, *pa2;
    cudaGetSymbolAddress((void**)&pP,    g_P);
    cudaGetSymbolAddress((void**)&pxhi,  g_xhi);
    cudaGetSymbolAddress((void**)&pxlo,  g_xlo);
    cudaGetSymbolAddress((void**)&pw6hi, g_w6hi);
    cudaGetSymbolAddress((void**)&pw6lo, g_w6lo);
    cudaGetSymbolAddress((void**)&pwo,   g_wo);
    cudaGetSymbolAddress((void**)&pa2,   g_a2);
    cudaGetSymbolAddress((void**)&pFc,   g_Fc);
    cudaGetSymbolAddress((void**)&pGc,   g_Gc);
    cudaGetSymbolAddress((void**)&pSc,   g_Sc);

    // smem (BM=64): (128+256)*80*2 = 61440 -> 3 CTAs/SM
    const int SMEM1 = (2 * 64 + 256) * RSTR * 2;
    cudaFuncSetAttribute((const void*)gemm_hmma<64, 4, 3>,
                         cudaFuncAttributeMaxDynamicSharedMemorySize, SMEM1);

    // conversions
    conv_x_kernel   <<<(MDIM * HDIM) / 256, 256>>>(x, pxhi, pxlo);
    conv_w6_kernel  <<<(NPROJ * HDIM) / 256, 256>>>(Wf, Wi, Wv, Wq, Wup, Wg, pw6hi, pw6lo);
    conv_wout_kernel<<<(HDIM * KOUT) / 256, 256>>>(Wro, Wd, pwo);

    // GEMM1 pass plan: f 3-pass (act=tanh, A+B corr), q/gc/h 1-pass.
    // actlut nibbles: f=9 q=0 gc=4,4 h=5,5 -> 0x554409.
    // blut: Blo pass ONLY for region 0 (f) -> 0x01.
    {
        dim3 grid(NPROJ / BN, MDIM / 64);   // (96, 128)
        gemm_hmma<64, 4, 3><<<grid, 128, SMEM1>>>(pxhi, pxlo, pw6hi, pw6lo, HDIM,
                                                  pP, PW, pa2, 0x554409u, 0x01u);
    }

    // scan
    {
        dim3 gA(RDIM / 256, 4 * NCH);
        scanA_kernel<<<gA, 256>>>(pP, pFc, pGc);
        scanB_kernel<<<32, 256>>>(pFc, pGc, init, pSc);
        scanC_kernel<<<gA, 256>>>(pP, pSc, pa2);
    }

    // GEMM2: out = [ro | h] @ Wout^T, single-pass fp16 both sides
    {
        dim3 grid(HDIM / BN, MDIM / 64);    // (8, 128)
        gemm_hmma<64, 4, 3><<<grid, 128, SMEM1>>>(pa2, pa2, pwo, pwo, KOUT,
                                                  out, HDIM, pa2, 0u, 0u);
    }
}

// round 12
// speedup vs baseline: 1.9204x; 1.0173x over previous
#include <cuda_runtime.h>
#include <cuda_fp16.h>
#include <stdint.h>
#include <math.h>

// ---------------- problem dims ----------------
#define MDIM 8192      // B*S
#define HDIM 1024
#define RDIM 2048
#define SDIM 2048
#define NPROJ 12288    // 6 * 2048 stacked projection outputs (GEMM1 N)
#define PW 6144        // P width after pair fusion: f | q | gc
#define KOUT 4096      // R + L for the output GEMM
#define NCH 64         // scan chunks
#define CH 32          // tokens per chunk

// ---------------- scratch (device globals) ----------------
__device__ float   g_P   [(size_t)MDIM * PW];              // f | q | gc
__device__ __half  g_xhi [(size_t)MDIM * HDIM];
__device__ __half  g_xlo [(size_t)MDIM * HDIM];
__device__ __half  g_w6hi[(size_t)NPROJ * HDIM];
__device__ __half  g_w6lo[(size_t)NPROJ * HDIM];
__device__ __half  g_wo  [(size_t)HDIM * KOUT];            // Wout single fp16
__device__ __half  g_a2  [(size_t)MDIM * KOUT];            // [ro | h], single fp16
__device__ float   g_Fc  [(size_t)4 * NCH * RDIM];
__device__ float   g_Gc  [(size_t)4 * NCH * RDIM];
__device__ float   g_Sc  [(size_t)4 * NCH * RDIM];

// ---------------- helpers ----------------
__device__ __forceinline__ uint32_t smem_u32(const void* p) {
    uint32_t a;
    asm("{ .reg .u64 t; cvta.to.shared.u64 t, %1; cvt.u32.u64 %0, t; }" : "=r"(a) : "l"(p));
    return a;
}
__device__ __forceinline__ void cp16(uint32_t s, const void* g) {
    asm volatile("cp.async.cg.shared.global [%0], [%1], 16;" :: "r"(s), "l"(g));
}
#define CP_COMMIT() asm volatile("cp.async.commit_group;" ::: "memory")
template<int N> __device__ __forceinline__ void cp_wait() {
    asm volatile("cp.async.wait_group %0;" :: "n"(N) : "memory");
}

__device__ __forceinline__ void ldm_x4(uint32_t (&d)[4], uint32_t a) {
    asm volatile("ldmatrix.sync.aligned.m8n8.x4.shared.b16 {%0,%1,%2,%3}, [%4];"
        : "=r"(d[0]), "=r"(d[1]), "=r"(d[2]), "=r"(d[3]) : "r"(a));
}
__device__ __forceinline__ void mma_f16(float (&c)[4], const uint32_t (&a)[4], const uint32_t* b) {
    asm volatile("mma.sync.aligned.m16n8k16.row.col.f32.f16.f16.f32 "
        "{%0,%1,%2,%3}, {%4,%5,%6,%7}, {%8,%9}, {%0,%1,%2,%3};"
        : "+f"(c[0]), "+f"(c[1]), "+f"(c[2]), "+f"(c[3])
        : "r"(a[0]), "r"(a[1]), "r"(a[2]), "r"(a[3]), "r"(b[0]), "r"(b[1]));
}

// ---------------- activations ----------------
#define ACT_NONE 0
#define ACT_TANH 1
#define ACT_GC 4     // pair: sigmoid(even) * silu(odd)   -> P (single col)
#define ACT_H  5     // pair: even * silu(odd)            -> a2 fp16

__device__ __forceinline__ float act_apply(float x, int act) {
    if (act == ACT_TANH) return tanhf(x);
    return x;
}
__device__ __forceinline__ float silu_f(float x) { return x / (1.0f + __expf(-x)); }
__device__ __forceinline__ float pair_act(float a, float b, int act) {
    if (act == ACT_GC) return (1.0f / (1.0f + __expf(-a))) * silu_f(b);
    return a * silu_f(b);   // ACT_H
}
__device__ __forceinline__ void split_fp16(float v, __half& hi, __half& lo) {
    hi = __float2half_rn(v);
    lo = __float2half_rn(v - __half2float(hi));
}

#define BN 128
#define KC 32
#define RSTR 80         // 64B row + 16B pad (20-bank stride, conflict-free)
#define BM 64

// ---------------- shared epilogue ----------------
__device__ __forceinline__ void epilogue_store(
    float (&acc)[4][4][4], int act, int bm, int bn, int colbase,
    int lane, int wn, float* C, int ldc, __half* aux)
{
    const int row0 = bm * BM + (lane >> 2);
    if (act < 4) {
        const int col0 = colbase + bn * BN + wn * 32 + 2 * (lane & 3);
#pragma unroll
        for (int mi = 0; mi < 4; mi++) {
#pragma unroll
            for (int nj = 0; nj < 4; nj++) {
                float2 v0, v1;
                v0.x = act_apply(acc[mi][nj][0], act);
                v0.y = act_apply(acc[mi][nj][1], act);
                v1.x = act_apply(acc[mi][nj][2], act);
                v1.y = act_apply(acc[mi][nj][3], act);
                size_t base = (size_t)(row0 + mi * 16) * ldc + col0 + nj * 8;
                *(float2*)(C + base)                   = v0;
                *(float2*)(C + base + (size_t)8 * ldc) = v1;
            }
        }
    } else {
        // pair regions: even/odd cols combined in-thread. Base from ACT
        // (gc/h each span TWO 2048-regions).
        const int pcbase = ((colbase + bn * BN) >> 1) - ((act == ACT_GC) ? 2048 : 4096);
        const int pc0 = pcbase + wn * 16 + (lane & 3);
#pragma unroll
        for (int mi = 0; mi < 4; mi++) {
#pragma unroll
            for (int nj = 0; nj < 4; nj++) {
                float v0 = pair_act(acc[mi][nj][0], acc[mi][nj][1], act);
                float v1 = pair_act(acc[mi][nj][2], acc[mi][nj][3], act);
                int pc = pc0 + nj * 4;
                int r  = row0 + mi * 16;
                if (act == ACT_GC) {
                    C[(size_t)r * ldc + 4096 + pc]       = v0;  // gc at P cols 4096..6144
                    C[(size_t)(r + 8) * ldc + 4096 + pc] = v1;
                } else {
                    aux[(size_t)r * KOUT + 2048 + pc]       = __float2half_rn(v0);
                    aux[(size_t)(r + 8) * KOUT + 2048 + pc] = __float2half_rn(v1);
                }
            }
        }
    }
}

// ================= 3-pass kernel (f region only) =================
// C = tanh(A*B^T) exact-ish: Ahi*Bhi + Alo*Bhi + Ahi*Blo.
__global__ void __launch_bounds__(128, 3)
gemm_3p(const __half* __restrict__ Ahi, const __half* __restrict__ Alo,
        const __half* __restrict__ Bhi, const __half* __restrict__ Blo,
        int K, float* __restrict__ C, int ldc)
{
    constexpr uint32_t OFF_AH = 0;
    constexpr uint32_t OFF_AL = BM * RSTR;
    constexpr uint32_t OFF_BH = 2 * BM * RSTR;
    constexpr uint32_t OFF_BL = (2 * BM + 128) * RSTR;
    constexpr uint32_t SB     = (2 * BM + 256) * RSTR;   // 30720

    extern __shared__ char smem[];
    const uint32_t sbase = smem_u32(smem);
    const int tid = threadIdx.x;
    const int bm  = blockIdx.y, bn = blockIdx.x;
    const int wn  = tid >> 5, lane = tid & 31;

    const __half* sA0 = Ahi + (size_t)bm * BM * K;
    const __half* sA1 = Alo + (size_t)bm * BM * K;
    const __half* sB0 = Bhi + (size_t)bn * BN * K;
    const __half* sB1 = Blo + (size_t)bn * BN * K;

    const int lcol = tid & 3, lrow0 = tid >> 2;

    auto load_stage = [&](int s) {
        const uint32_t sb = sbase + (uint32_t)(s & 1) * SB + lcol * 16;
        const int k0 = s * KC + lcol * 8;
#pragma unroll
        for (int i = 0; i < 2; i++) {
            int row = lrow0 + 32 * i;
            cp16(sb + OFF_AH + row * RSTR, sA0 + (size_t)row * K + k0);
            cp16(sb + OFF_AL + row * RSTR, sA1 + (size_t)row * K + k0);
        }
#pragma unroll
        for (int i = 0; i < 4; i++) {
            int row = lrow0 + 32 * i;
            cp16(sb + OFF_BH + row * RSTR, sB0 + (size_t)row * K + k0);
            cp16(sb + OFF_BL + row * RSTR, sB1 + (size_t)row * K + k0);
        }
    };

    const int quad = lane >> 3, r8 = lane & 7;
    const uint32_t aoff = (uint32_t)((r8 + (quad & 1) * 8) * RSTR + (quad >> 1) * 16);
    const uint32_t boff = (uint32_t)((wn * 32 + r8 + (quad >> 1) * 8) * RSTR + (quad & 1) * 16);

    float acc[4][4][4];
#pragma unroll
    for (int mi = 0; mi < 4; mi++)
#pragma unroll
        for (int nj = 0; nj < 4; nj++)
#pragma unroll
            for (int e = 0; e < 4; e++) acc[mi][nj][e] = 0.0f;

    const int ns = K / KC;
    load_stage(0); CP_COMMIT();

    for (int s = 0; s < ns; s++) {
        if (s + 1 < ns) load_stage(s + 1);
        CP_COMMIT();
        cp_wait<1>();
        __syncthreads();

        const uint32_t st = sbase + (uint32_t)(s & 1) * SB;
        const uint32_t aH = st + OFF_AH + aoff;
        const uint32_t aL = st + OFF_AL + aoff;
        const uint32_t bH = st + OFF_BH + boff;
        const uint32_t bL = st + OFF_BL + boff;

#pragma unroll
        for (int ks = 0; ks < 2; ks++) {
            const uint32_t kb = ks * 32;
            uint32_t afh[4][4], bf[4][2];
#pragma unroll
            for (int mi = 0; mi < 4; mi++) ldm_x4(afh[mi], aH + mi * (16 * RSTR) + kb);
#pragma unroll
            for (int t = 0; t < 2; t++) {
                uint32_t tt[4];
                ldm_x4(tt, bH + t * (16 * RSTR) + kb);
                bf[2 * t][0] = tt[0]; bf[2 * t][1] = tt[1];
                bf[2 * t + 1][0] = tt[2]; bf[2 * t + 1][1] = tt[3];
            }
#pragma unroll
            for (int mi = 0; mi < 4; mi++)
#pragma unroll
                for (int nj = 0; nj < 4; nj++) mma_f16(acc[mi][nj], afh[mi], bf[nj]);
            {
                uint32_t afl[4][4];
#pragma unroll
                for (int mi = 0; mi < 4; mi++) ldm_x4(afl[mi], aL + mi * (16 * RSTR) + kb);
#pragma unroll
                for (int mi = 0; mi < 4; mi++)
#pragma unroll
                    for (int nj = 0; nj < 4; nj++) mma_f16(acc[mi][nj], afl[mi], bf[nj]);
            }
#pragma unroll
            for (int t = 0; t < 2; t++) {
                uint32_t tt[4];
                ldm_x4(tt, bL + t * (16 * RSTR) + kb);
                bf[2 * t][0] = tt[0]; bf[2 * t][1] = tt[1];
                bf[2 * t + 1][0] = tt[2]; bf[2 * t + 1][1] = tt[3];
            }
#pragma unroll
            for (int mi = 0; mi < 4; mi++)
#pragma unroll
                for (int nj = 0; nj < 4; nj++) mma_f16(acc[mi][nj], afh[mi], bf[nj]);
        }
        __syncthreads();
    }

    epilogue_store(acc, ACT_TANH, bm, bn, 0, lane, wn, C, ldc, ((__half*)0));
}

// ================= slim 1-pass kernel (q/gc/h + GEMM2) =================
// C = act(A*B^T), single fp16 pass. Small smem (30.7KB) + reg cap -> 5 CTAs/SM.
__global__ void __launch_bounds__(128, 5)
gemm_1p(const __half* __restrict__ A, const __half* __restrict__ B,
        int K, float* __restrict__ C, int ldc,
        __half* __restrict__ aux, unsigned actlut, int colbase)
{
    constexpr uint32_t OFF_B = BM * RSTR;
    constexpr uint32_t SB    = (BM + 128) * RSTR;     // 15360

    extern __shared__ char smem[];
    const uint32_t sbase = smem_u32(smem);
    const int tid = threadIdx.x;
    const int bm  = blockIdx.y, bn = blockIdx.x;
    const int wn  = tid >> 5, lane = tid & 31;

    const int region = (colbase + bn * BN) >> 11;
    const int act    = (int)((actlut >> (region * 4)) & 15u);

    const __half* sA = A + (size_t)bm * BM * K;
    const __half* sB = B + (size_t)bn * BN * K;

    const int lcol = tid & 3, lrow0 = tid >> 2;

    auto load_stage = [&](int s) {
        const uint32_t sb = sbase + (uint32_t)(s & 1) * SB + lcol * 16;
        const int k0 = s * KC + lcol * 8;
#pragma unroll
        for (int i = 0; i < 2; i++) {
            int row = lrow0 + 32 * i;
            cp16(sb + row * RSTR, sA + (size_t)row * K + k0);
        }
#pragma unroll
        for (int i = 0; i < 4; i++) {
            int row = lrow0 + 32 * i;
            cp16(sb + OFF_B + row * RSTR, sB + (size_t)row * K + k0);
        }
    };

    const int quad = lane >> 3, r8 = lane & 7;
    const uint32_t aoff = (uint32_t)((r8 + (quad & 1) * 8) * RSTR + (quad >> 1) * 16);
    const uint32_t boff = (uint32_t)(OFF_B + (wn * 32 + r8 + (quad >> 1) * 8) * RSTR + (quad & 1) * 16);

    float acc[4][4][4];
#pragma unroll
    for (int mi = 0; mi < 4; mi++)
#pragma unroll
        for (int nj = 0; nj < 4; nj++)
#pragma unroll
            for (int e = 0; e < 4; e++) acc[mi][nj][e] = 0.0f;

    const int ns = K / KC;
    load_stage(0); CP_COMMIT();

    for (int s = 0; s < ns; s++) {
        if (s + 1 < ns) load_stage(s + 1);
        CP_COMMIT();
        cp_wait<1>();
        __syncthreads();

        const uint32_t st = sbase + (uint32_t)(s & 1) * SB;
        const uint32_t aH = st + aoff;
        const uint32_t bH = st + boff;

#pragma unroll
        for (int ks = 0; ks < 2; ks++) {
            const uint32_t kb = ks * 32;
            uint32_t afh[4][4], bf[4][2];
#pragma unroll
            for (int mi = 0; mi < 4; mi++) ldm_x4(afh[mi], aH + mi * (16 * RSTR) + kb);
#pragma unroll
            for (int t = 0; t < 2; t++) {
                uint32_t tt[4];
                ldm_x4(tt, bH + t * (16 * RSTR) + kb);
                bf[2 * t][0] = tt[0]; bf[2 * t][1] = tt[1];
                bf[2 * t + 1][0] = tt[2]; bf[2 * t + 1][1] = tt[3];
            }
#pragma unroll
            for (int mi = 0; mi < 4; mi++)
#pragma unroll
                for (int nj = 0; nj < 4; nj++) mma_f16(acc[mi][nj], afh[mi], bf[nj]);
        }
        __syncthreads();
    }

    epilogue_store(acc, act, bm, bn, colbase, lane, wn, C, ldc, aux);
}

// ================= conversion kernels =================
__global__ void conv_x_kernel(const float* __restrict__ x,
                              __half* __restrict__ hi, __half* __restrict__ lo) {
    size_t i = (size_t)blockIdx.x * blockDim.x + threadIdx.x;
    split_fp16(x[i], hi[i], lo[i]);
}

// W6 stacking: [f(0:2048) | q(2048:4096) | g:c interleaved(4096:8192) | up:gate interleaved(8192:12288)]
__global__ void conv_w6_kernel(const float* __restrict__ Wf, const float* __restrict__ Wi,
                               const float* __restrict__ Wv, const float* __restrict__ Wq,
                               const float* __restrict__ Wup, const float* __restrict__ Wg,
                               __half* __restrict__ hi, __half* __restrict__ lo) {
    size_t i = (size_t)blockIdx.x * blockDim.x + threadIdx.x;     // [0, 12288*1024)
    int n = (int)(i >> 10);
    int k = (int)(i & 1023);
    const float* src;
    int r;
    if (n < 2048)       { src = Wf; r = n; }
    else if (n < 4096)  { src = Wq; r = n - 2048; }
    else if (n < 8192)  { r = (n - 4096) >> 1; src = (n & 1) ? Wv : Wi; }
    else                { r = (n - 8192) >> 1; src = (n & 1) ? Wg : Wup; }
    split_fp16(src[(size_t)r * 1024 + k], hi[i], lo[i]);
}

__global__ void conv_wout_kernel(const float* __restrict__ Wro, const float* __restrict__ Wd,
                                 __half* __restrict__ w) {
    size_t i = (size_t)blockIdx.x * blockDim.x + threadIdx.x;     // [0, 1024*4096)
    int h = (int)(i >> 12);
    int j = (int)(i & 4095);
    float v = (j < 2048) ? Wro[(size_t)h * 2048 + j] : Wd[(size_t)h * 2048 + (j - 2048)];
    w[i] = __float2half_rn(v);
}

// ================= scan (two-level, chunked) =================
// P cols: f[0:2048)  q[2048:4096)  gc[4096:6144)
__global__ void scanA_kernel(const float* __restrict__ P,
                             float* __restrict__ Fc, float* __restrict__ Gc) {
    int r  = blockIdx.x * blockDim.x + threadIdx.x;
    int bc = blockIdx.y;
    int b = bc >> 6, ch = bc & 63;
    const float* row = P + (size_t)(b * SDIM + ch * CH) * PW;
    float F = 1.0f, G = 0.0f;
#pragma unroll 4
    for (int t = 0; t < CH; t++) {
        float f  = row[r];
        float gc = row[4096 + r];
        G = fmaf(f, G, gc);
        F *= f;
        row += PW;
    }
    Fc[(size_t)bc * RDIM + r] = F;
    Gc[(size_t)bc * RDIM + r] = G;
}

__global__ void scanB_kernel(const float* __restrict__ Fc, const float* __restrict__ Gc,
                             const float* __restrict__ init, float* __restrict__ Sc) {
    int i = blockIdx.x * blockDim.x + threadIdx.x;
    int b = i >> 11, r = i & 2047;
    float state = init[r];
    for (int ch = 0; ch < NCH; ch++) {
        size_t idx = (size_t)(b * NCH + ch) * RDIM + r;
        Sc[idx] = state;
        state = fmaf(Fc[idx], state, Gc[idx]);
    }
}

__global__ void scanC_kernel(const float* __restrict__ P, const float* __restrict__ Sc,
                             __half* __restrict__ a2) {
    int r  = blockIdx.x * blockDim.x + threadIdx.x;
    int bc = blockIdx.y;
    int b = bc >> 6, ch = bc & 63;
    int m0 = b * SDIM + ch * CH;
    const float* row = P + (size_t)m0 * PW;
    float state = Sc[(size_t)bc * RDIM + r];
#pragma unroll 4
    for (int t = 0; t < CH; t++) {
        float f  = row[r];
        float q  = row[2048 + r];
        float gc = row[4096 + r];
        state = fmaf(f, state, gc);
        float z = q * state;
        float ro = z / (1.0f + __expf(-z));
        a2[(size_t)(m0 + t) * KOUT + r] = __float2half_rn(ro);
        row += PW;
    }
}

// ================= launch =================
extern "C" void kernel_launch(void* const* d_in, const int* in_sizes, int n_in,
                              void* d_out, int out_size)
{
    const float* x    = (const float*)d_in[0];
    const float* Wf   = (const float*)d_in[1];
    const float* Wi   = (const float*)d_in[2];
    const float* Wv   = (const float*)d_in[3];
    const float* Wq   = (const float*)d_in[4];
    const float* Wro  = (const float*)d_in[5];
    const float* Wup  = (const float*)d_in[6];
    const float* Wg   = (const float*)d_in[7];
    const float* Wd   = (const float*)d_in[8];
    const float* init = (const float*)d_in[9];
    float* out = (float*)d_out;

    float *pP, *pFc, *pGc, *pSc;
    __half *pxhi, *pxlo, *pw6hi, *pw6lo, *pwo, *pa2;
    cudaGetSymbolAddress((void**)&pP,    g_P);
    cudaGetSymbolAddress((void**)&pxhi,  g_xhi);
    cudaGetSymbolAddress((void**)&pxlo,  g_xlo);
    cudaGetSymbolAddress((void**)&pw6hi, g_w6hi);
    cudaGetSymbolAddress((void**)&pw6lo, g_w6lo);
    cudaGetSymbolAddress((void**)&pwo,   g_wo);
    cudaGetSymbolAddress((void**)&pa2,   g_a2);
    cudaGetSymbolAddress((void**)&pFc,   g_Fc);
    cudaGetSymbolAddress((void**)&pGc,   g_Gc);
    cudaGetSymbolAddress((void**)&pSc,   g_Sc);

    const int SMEM3 = (2 * BM + 256) * RSTR * 2;  // 61440, 3-pass kernel
    const int SMEM1 = (BM + 128) * RSTR * 2;      // 30720, 1-pass kernel
    cudaFuncSetAttribute((const void*)gemm_3p,
                         cudaFuncAttributeMaxDynamicSharedMemorySize, SMEM3);
    cudaFuncSetAttribute((const void*)gemm_1p,
                         cudaFuncAttributeMaxDynamicSharedMemorySize, SMEM1);

    // conversions
    conv_x_kernel   <<<(MDIM * HDIM) / 256, 256>>>(x, pxhi, pxlo);
    conv_w6_kernel  <<<(NPROJ * HDIM) / 256, 256>>>(Wf, Wi, Wv, Wq, Wup, Wg, pw6hi, pw6lo);
    conv_wout_kernel<<<(HDIM * KOUT) / 256, 256>>>(Wro, Wd, pwo);

    // GEMM1-f: 3-pass exact, tanh, P cols 0..2047
    {
        dim3 grid(RDIM / BN, MDIM / BM);    // (16, 128)
        gemm_3p<<<grid, 128, SMEM3>>>(pxhi, pxlo, pw6hi, pw6lo, HDIM, pP, PW);
    }
    // GEMM1-rest: 1-pass, cols 2048..12287 (q / gc / h)
    // actlut (global region nibbles): r1 q=0, r2,3 gc=4, r4,5 h=5 -> 0x554400
    {
        dim3 grid((NPROJ - RDIM) / BN, MDIM / BM);   // (80, 128)
        gemm_1p<<<grid, 128, SMEM1>>>(pxhi, pw6hi + (size_t)RDIM * HDIM, HDIM,
                                      pP, PW, pa2, 0x554400u, RDIM);
    }

    // scan
    {
        dim3 gA(RDIM / 256, 4 * NCH);
        scanA_kernel<<<gA, 256>>>(pP, pFc, pGc);
        scanB_kernel<<<32, 256>>>(pFc, pGc, init, pSc);
        scanC_kernel<<<gA, 256>>>(pP, pSc, pa2);
    }

    // GEMM2: out = [ro | h] @ Wout^T, single-pass fp16
    {
        dim3 grid(HDIM / BN, MDIM / BM);    // (8, 128)
        gemm_1p<<<grid, 128, SMEM1>>>(pa2, pwo, KOUT, out, HDIM, pa2, 0u, 0);
    }
}

// round 13
// speedup vs baseline: 2.0918x; 1.0893x over previous
#include <cuda_runtime.h>
#include <cuda_fp16.h>
#include <stdint.h>
#include <math.h>

// ---------------- problem dims ----------------
#define MDIM 8192      // B*S
#define HDIM 1024
#define RDIM 2048
#define SDIM 2048
#define NPROJ 12288    // 6 * 2048 stacked projection outputs (GEMM1 N)
#define PW 6144        // P width after pair fusion: f | q | gc
#define KOUT 4096      // R + L for the output GEMM
#define NCH 64         // scan chunks
#define CH 32          // tokens per chunk

// ---------------- scratch (device globals) ----------------
__device__ float   g_P   [(size_t)MDIM * PW];              // f | q | gc
__device__ __half  g_xhi [(size_t)MDIM * HDIM];
__device__ __half  g_xlo [(size_t)MDIM * HDIM];
__device__ __half  g_w6hi[(size_t)NPROJ * HDIM];
__device__ __half  g_w6lo[(size_t)NPROJ * HDIM];
__device__ __half  g_wo  [(size_t)HDIM * KOUT];            // Wout single fp16
__device__ __half  g_a2  [(size_t)MDIM * KOUT];            // [ro | h], single fp16
__device__ float   g_Fc  [(size_t)4 * NCH * RDIM];
__device__ float   g_Gc  [(size_t)4 * NCH * RDIM];
__device__ float   g_Sc  [(size_t)4 * NCH * RDIM];

// ---------------- helpers ----------------
__device__ __forceinline__ uint32_t smem_u32(const void* p) {
    uint32_t a;
    asm("{ .reg .u64 t; cvta.to.shared.u64 t, %1; cvt.u32.u64 %0, t; }" : "=r"(a) : "l"(p));
    return a;
}
__device__ __forceinline__ void cp16(uint32_t s, const void* g) {
    asm volatile("cp.async.cg.shared.global [%0], [%1], 16;" :: "r"(s), "l"(g));
}
#define CP_COMMIT() asm volatile("cp.async.commit_group;" ::: "memory")
template<int N> __device__ __forceinline__ void cp_wait() {
    asm volatile("cp.async.wait_group %0;" :: "n"(N) : "memory");
}

__device__ __forceinline__ void ldm_x4(uint32_t (&d)[4], uint32_t a) {
    asm volatile("ldmatrix.sync.aligned.m8n8.x4.shared.b16 {%0,%1,%2,%3}, [%4];"
        : "=r"(d[0]), "=r"(d[1]), "=r"(d[2]), "=r"(d[3]) : "r"(a));
}
__device__ __forceinline__ void mma_f16(float (&c)[4], const uint32_t (&a)[4], const uint32_t* b) {
    asm volatile("mma.sync.aligned.m16n8k16.row.col.f32.f16.f16.f32 "
        "{%0,%1,%2,%3}, {%4,%5,%6,%7}, {%8,%9}, {%0,%1,%2,%3};"
        : "+f"(c[0]), "+f"(c[1]), "+f"(c[2]), "+f"(c[3])
        : "r"(a[0]), "r"(a[1]), "r"(a[2]), "r"(a[3]), "r"(b[0]), "r"(b[1]));
}

// ---------------- activations ----------------
#define ACT_NONE 0
#define ACT_TANH 1
#define ACT_GC 4     // pair: sigmoid(even) * silu(odd)   -> P (single col)
#define ACT_H  5     // pair: even * silu(odd)            -> a2 fp16

__device__ __forceinline__ float act_apply(float x, int act) {
    if (act == ACT_TANH) return tanhf(x);
    return x;
}
__device__ __forceinline__ float silu_f(float x) { return x / (1.0f + __expf(-x)); }
__device__ __forceinline__ float pair_act(float a, float b, int act) {
    if (act == ACT_GC) return (1.0f / (1.0f + __expf(-a))) * silu_f(b);
    return a * silu_f(b);   // ACT_H
}
__device__ __forceinline__ void split_fp16(float v, __half& hi, __half& lo) {
    hi = __float2half_rn(v);
    lo = __float2half_rn(v - __half2float(hi));
}

#define BN 128
#define KC 32
#define RSTR 80         // 64B row + 16B pad (20-bank stride, conflict-free)
#define BM 64

// ---------------- shared epilogue ----------------
__device__ __forceinline__ void epilogue_store(
    float (&acc)[4][4][4], int act, int bm, int bn, int colbase,
    int lane, int wn, float* C, int ldc, __half* aux)
{
    const int row0 = bm * BM + (lane >> 2);
    if (act < 4) {
        const int col0 = colbase + bn * BN + wn * 32 + 2 * (lane & 3);
#pragma unroll
        for (int mi = 0; mi < 4; mi++) {
#pragma unroll
            for (int nj = 0; nj < 4; nj++) {
                float2 v0, v1;
                v0.x = act_apply(acc[mi][nj][0], act);
                v0.y = act_apply(acc[mi][nj][1], act);
                v1.x = act_apply(acc[mi][nj][2], act);
                v1.y = act_apply(acc[mi][nj][3], act);
                size_t base = (size_t)(row0 + mi * 16) * ldc + col0 + nj * 8;
                *(float2*)(C + base)                   = v0;
                *(float2*)(C + base + (size_t)8 * ldc) = v1;
            }
        }
    } else {
        // pair regions: even/odd cols combined in-thread. Base from ACT
        // (gc/h each span TWO 2048-regions).
        const int pcbase = ((colbase + bn * BN) >> 1) - ((act == ACT_GC) ? 2048 : 4096);
        const int pc0 = pcbase + wn * 16 + (lane & 3);
#pragma unroll
        for (int mi = 0; mi < 4; mi++) {
#pragma unroll
            for (int nj = 0; nj < 4; nj++) {
                float v0 = pair_act(acc[mi][nj][0], acc[mi][nj][1], act);
                float v1 = pair_act(acc[mi][nj][2], acc[mi][nj][3], act);
                int pc = pc0 + nj * 4;
                int r  = row0 + mi * 16;
                if (act == ACT_GC) {
                    C[(size_t)r * ldc + 4096 + pc]       = v0;  // gc at P cols 4096..6144
                    C[(size_t)(r + 8) * ldc + 4096 + pc] = v1;
                } else {
                    aux[(size_t)r * KOUT + 2048 + pc]       = __float2half_rn(v0);
                    aux[(size_t)(r + 8) * KOUT + 2048 + pc] = __float2half_rn(v1);
                }
            }
        }
    }
}

// ================= 2-pass kernel (f region only) =================
// C = tanh((Ahi+Alo)*Bhi^T): x-side exact, weight-lo dropped (error model:
// ~1.5e-4 pre-tanh, x2.4-4 recurrence amplification -> ~3-4e-4 contribution).
__global__ void __launch_bounds__(128, 4)
gemm_2p(const __half* __restrict__ Ahi, const __half* __restrict__ Alo,
        const __half* __restrict__ Bhi,
        int K, float* __restrict__ C, int ldc)
{
    constexpr uint32_t OFF_AL = BM * RSTR;
    constexpr uint32_t OFF_B  = 2 * BM * RSTR;
    constexpr uint32_t SB     = (2 * BM + 128) * RSTR;   // 20480

    extern __shared__ char smem[];
    const uint32_t sbase = smem_u32(smem);
    const int tid = threadIdx.x;
    const int bm  = blockIdx.y, bn = blockIdx.x;
    const int wn  = tid >> 5, lane = tid & 31;

    const __half* sA0 = Ahi + (size_t)bm * BM * K;
    const __half* sA1 = Alo + (size_t)bm * BM * K;
    const __half* sB0 = Bhi + (size_t)bn * BN * K;

    const int lcol = tid & 3, lrow0 = tid >> 2;

    auto load_stage = [&](int s) {
        const uint32_t sb = sbase + (uint32_t)(s & 1) * SB + lcol * 16;
        const int k0 = s * KC + lcol * 8;
#pragma unroll
        for (int i = 0; i < 2; i++) {
            int row = lrow0 + 32 * i;
            cp16(sb + row * RSTR,          sA0 + (size_t)row * K + k0);
            cp16(sb + OFF_AL + row * RSTR, sA1 + (size_t)row * K + k0);
        }
#pragma unroll
        for (int i = 0; i < 4; i++) {
            int row = lrow0 + 32 * i;
            cp16(sb + OFF_B + row * RSTR, sB0 + (size_t)row * K + k0);
        }
    };

    const int quad = lane >> 3, r8 = lane & 7;
    const uint32_t aoff = (uint32_t)((r8 + (quad & 1) * 8) * RSTR + (quad >> 1) * 16);
    const uint32_t boff = (uint32_t)(OFF_B + (wn * 32 + r8 + (quad >> 1) * 8) * RSTR + (quad & 1) * 16);

    float acc[4][4][4];
#pragma unroll
    for (int mi = 0; mi < 4; mi++)
#pragma unroll
        for (int nj = 0; nj < 4; nj++)
#pragma unroll
            for (int e = 0; e < 4; e++) acc[mi][nj][e] = 0.0f;

    const int ns = K / KC;
    load_stage(0); CP_COMMIT();

    for (int s = 0; s < ns; s++) {
        if (s + 1 < ns) load_stage(s + 1);
        CP_COMMIT();
        cp_wait<1>();
        __syncthreads();

        const uint32_t st = sbase + (uint32_t)(s & 1) * SB;
        const uint32_t aH = st + aoff;
        const uint32_t aL = st + OFF_AL + aoff;
        const uint32_t bH = st + boff;

#pragma unroll
        for (int ks = 0; ks < 2; ks++) {
            const uint32_t kb = ks * 32;
            uint32_t afh[4][4], bf[4][2];
#pragma unroll
            for (int mi = 0; mi < 4; mi++) ldm_x4(afh[mi], aH + mi * (16 * RSTR) + kb);
#pragma unroll
            for (int t = 0; t < 2; t++) {
                uint32_t tt[4];
                ldm_x4(tt, bH + t * (16 * RSTR) + kb);
                bf[2 * t][0] = tt[0]; bf[2 * t][1] = tt[1];
                bf[2 * t + 1][0] = tt[2]; bf[2 * t + 1][1] = tt[3];
            }
#pragma unroll
            for (int mi = 0; mi < 4; mi++)
#pragma unroll
                for (int nj = 0; nj < 4; nj++) mma_f16(acc[mi][nj], afh[mi], bf[nj]);
            {
                uint32_t afl[4][4];
#pragma unroll
                for (int mi = 0; mi < 4; mi++) ldm_x4(afl[mi], aL + mi * (16 * RSTR) + kb);
#pragma unroll
                for (int mi = 0; mi < 4; mi++)
#pragma unroll
                    for (int nj = 0; nj < 4; nj++) mma_f16(acc[mi][nj], afl[mi], bf[nj]);
            }
        }
        __syncthreads();
    }

    epilogue_store(acc, ACT_TANH, bm, bn, 0, lane, wn, C, ldc, ((__half*)0));
}

// ================= slim 1-pass kernel (q/gc/h + GEMM2) =================
// OCC=4 -> reg cap 128 (>= ~120 needed): NO spill (OCC=5 capped at 102 and
// spilled the mainloop last round).
__global__ void __launch_bounds__(128, 4)
gemm_1p(const __half* __restrict__ A, const __half* __restrict__ B,
        int K, float* __restrict__ C, int ldc,
        __half* __restrict__ aux, unsigned actlut, int colbase)
{
    constexpr uint32_t OFF_B = BM * RSTR;
    constexpr uint32_t SB    = (BM + 128) * RSTR;     // 15360

    extern __shared__ char smem[];
    const uint32_t sbase = smem_u32(smem);
    const int tid = threadIdx.x;
    const int bm  = blockIdx.y, bn = blockIdx.x;
    const int wn  = tid >> 5, lane = tid & 31;

    const int region = (colbase + bn * BN) >> 11;
    const int act    = (int)((actlut >> (region * 4)) & 15u);

    const __half* sA = A + (size_t)bm * BM * K;
    const __half* sB = B + (size_t)bn * BN * K;

    const int lcol = tid & 3, lrow0 = tid >> 2;

    auto load_stage = [&](int s) {
        const uint32_t sb = sbase + (uint32_t)(s & 1) * SB + lcol * 16;
        const int k0 = s * KC + lcol * 8;
#pragma unroll
        for (int i = 0; i < 2; i++) {
            int row = lrow0 + 32 * i;
            cp16(sb + row * RSTR, sA + (size_t)row * K + k0);
        }
#pragma unroll
        for (int i = 0; i < 4; i++) {
            int row = lrow0 + 32 * i;
            cp16(sb + OFF_B + row * RSTR, sB + (size_t)row * K + k0);
        }
    };

    const int quad = lane >> 3, r8 = lane & 7;
    const uint32_t aoff = (uint32_t)((r8 + (quad & 1) * 8) * RSTR + (quad >> 1) * 16);
    const uint32_t boff = (uint32_t)(OFF_B + (wn * 32 + r8 + (quad >> 1) * 8) * RSTR + (quad & 1) * 16);

    float acc[4][4][4];
#pragma unroll
    for (int mi = 0; mi < 4; mi++)
#pragma unroll
        for (int nj = 0; nj < 4; nj++)
#pragma unroll
            for (int e = 0; e < 4; e++) acc[mi][nj][e] = 0.0f;

    const int ns = K / KC;
    load_stage(0); CP_COMMIT();

    for (int s = 0; s < ns; s++) {
        if (s + 1 < ns) load_stage(s + 1);
        CP_COMMIT();
        cp_wait<1>();
        __syncthreads();

        const uint32_t st = sbase + (uint32_t)(s & 1) * SB;
        const uint32_t aH = st + aoff;
        const uint32_t bH = st + boff;

#pragma unroll
        for (int ks = 0; ks < 2; ks++) {
            const uint32_t kb = ks * 32;
            uint32_t afh[4][4], bf[4][2];
#pragma unroll
            for (int mi = 0; mi < 4; mi++) ldm_x4(afh[mi], aH + mi * (16 * RSTR) + kb);
#pragma unroll
            for (int t = 0; t < 2; t++) {
                uint32_t tt[4];
                ldm_x4(tt, bH + t * (16 * RSTR) + kb);
                bf[2 * t][0] = tt[0]; bf[2 * t][1] = tt[1];
                bf[2 * t + 1][0] = tt[2]; bf[2 * t + 1][1] = tt[3];
            }
#pragma unroll
            for (int mi = 0; mi < 4; mi++)
#pragma unroll
                for (int nj = 0; nj < 4; nj++) mma_f16(acc[mi][nj], afh[mi], bf[nj]);
        }
        __syncthreads();
    }

    epilogue_store(acc, act, bm, bn, colbase, lane, wn, C, ldc, aux);
}

// ================= conversion kernels =================
__global__ void conv_x_kernel(const float* __restrict__ x,
                              __half* __restrict__ hi, __half* __restrict__ lo) {
    size_t i = (size_t)blockIdx.x * blockDim.x + threadIdx.x;
    split_fp16(x[i], hi[i], lo[i]);
}

// W6 stacking: [f(0:2048) | q(2048:4096) | g:c interleaved(4096:8192) | up:gate interleaved(8192:12288)]
__global__ void conv_w6_kernel(const float* __restrict__ Wf, const float* __restrict__ Wi,
                               const float* __restrict__ Wv, const float* __restrict__ Wq,
                               const float* __restrict__ Wup, const float* __restrict__ Wg,
                               __half* __restrict__ hi, __half* __restrict__ lo) {
    size_t i = (size_t)blockIdx.x * blockDim.x + threadIdx.x;     // [0, 12288*1024)
    int n = (int)(i >> 10);
    int k = (int)(i & 1023);
    const float* src;
    int r;
    if (n < 2048)       { src = Wf; r = n; }
    else if (n < 4096)  { src = Wq; r = n - 2048; }
    else if (n < 8192)  { r = (n - 4096) >> 1; src = (n & 1) ? Wv : Wi; }
    else                { r = (n - 8192) >> 1; src = (n & 1) ? Wg : Wup; }
    split_fp16(src[(size_t)r * 1024 + k], hi[i], lo[i]);
}

__global__ void conv_wout_kernel(const float* __restrict__ Wro, const float* __restrict__ Wd,
                                 __half* __restrict__ w) {
    size_t i = (size_t)blockIdx.x * blockDim.x + threadIdx.x;     // [0, 1024*4096)
    int h = (int)(i >> 12);
    int j = (int)(i & 4095);
    float v = (j < 2048) ? Wro[(size_t)h * 2048 + j] : Wd[(size_t)h * 2048 + (j - 2048)];
    w[i] = __float2half_rn(v);
}

// ================= scan (two-level, chunked) =================
// P cols: f[0:2048)  q[2048:4096)  gc[4096:6144)
__global__ void scanA_kernel(const float* __restrict__ P,
                             float* __restrict__ Fc, float* __restrict__ Gc) {
    int r  = blockIdx.x * blockDim.x + threadIdx.x;
    int bc = blockIdx.y;
    int b = bc >> 6, ch = bc & 63;
    const float* row = P + (size_t)(b * SDIM + ch * CH) * PW;
    float F = 1.0f, G = 0.0f;
#pragma unroll 4
    for (int t = 0; t < CH; t++) {
        float f  = row[r];
        float gc = row[4096 + r];
        G = fmaf(f, G, gc);
        F *= f;
        row += PW;
    }
    Fc[(size_t)bc * RDIM + r] = F;
    Gc[(size_t)bc * RDIM + r] = G;
}

__global__ void scanB_kernel(const float* __restrict__ Fc, const float* __restrict__ Gc,
                             const float* __restrict__ init, float* __restrict__ Sc) {
    int i = blockIdx.x * blockDim.x + threadIdx.x;
    int b = i >> 11, r = i & 2047;
    float state = init[r];
    for (int ch = 0; ch < NCH; ch++) {
        size_t idx = (size_t)(b * NCH + ch) * RDIM + r;
        Sc[idx] = state;
        state = fmaf(Fc[idx], state, Gc[idx]);
    }
}

__global__ void scanC_kernel(const float* __restrict__ P, const float* __restrict__ Sc,
                             __half* __restrict__ a2) {
    int r  = blockIdx.x * blockDim.x + threadIdx.x;
    int bc = blockIdx.y;
    int b = bc >> 6, ch = bc & 63;
    int m0 = b * SDIM + ch * CH;
    const float* row = P + (size_t)m0 * PW;
    float state = Sc[(size_t)bc * RDIM + r];
#pragma unroll 4
    for (int t = 0; t < CH; t++) {
        float f  = row[r];
        float q  = row[2048 + r];
        float gc = row[4096 + r];
        state = fmaf(f, state, gc);
        float z = q * state;
        float ro = z / (1.0f + __expf(-z));
        a2[(size_t)(m0 + t) * KOUT + r] = __float2half_rn(ro);
        row += PW;
    }
}

// ================= launch =================
extern "C" void kernel_launch(void* const* d_in, const int* in_sizes, int n_in,
                              void* d_out, int out_size)
{
    const float* x    = (const float*)d_in[0];
    const float* Wf   = (const float*)d_in[1];
    const float* Wi   = (const float*)d_in[2];
    const float* Wv   = (const float*)d_in[3];
    const float* Wq   = (const float*)d_in[4];
    const float* Wro  = (const float*)d_in[5];
    const float* Wup  = (const float*)d_in[6];
    const float* Wg   = (const float*)d_in[7];
    const float* Wd   = (const float*)d_in[8];
    const float* init = (const float*)d_in[9];
    float* out = (float*)d_out;

    float *pP, *pFc, *pGc, *pSc;
    __half *pxhi, *pxlo, *pw6hi, *pw6lo, *pwo, *pa2;
    cudaGetSymbolAddress((void**)&pP,    g_P);
    cudaGetSymbolAddress((void**)&pxhi,  g_xhi);
    cudaGetSymbolAddress((void**)&pxlo,  g_xlo);
    cudaGetSymbolAddress((void**)&pw6hi, g_w6hi);
    cudaGetSymbolAddress((void**)&pw6lo, g_w6lo);
    cudaGetSymbolAddress((void**)&pwo,   g_wo);
    cudaGetSymbolAddress((void**)&pa2,   g_a2);
    cudaGetSymbolAddress((void**)&pFc,   g_Fc);
    cudaGetSymbolAddress((void**)&pGc,   g_Gc);
    cudaGetSymbolAddress((void**)&pSc,   g_Sc);

    const int SMEM2P = (2 * BM + 128) * RSTR * 2;  // 40960, 2-pass f kernel
    const int SMEM1P = (BM + 128) * RSTR * 2;      // 30720, 1-pass kernel
    cudaFuncSetAttribute((const void*)gemm_2p,
                         cudaFuncAttributeMaxDynamicSharedMemorySize, SMEM2P);
    cudaFuncSetAttribute((const void*)gemm_1p,
                         cudaFuncAttributeMaxDynamicSharedMemorySize, SMEM1P);

    // conversions
    conv_x_kernel   <<<(MDIM * HDIM) / 256, 256>>>(x, pxhi, pxlo);
    conv_w6_kernel  <<<(NPROJ * HDIM) / 256, 256>>>(Wf, Wi, Wv, Wq, Wup, Wg, pw6hi, pw6lo);
    conv_wout_kernel<<<(HDIM * KOUT) / 256, 256>>>(Wro, Wd, pwo);

    // GEMM1-f: 2-pass (x exact, weight-lo dropped), tanh, P cols 0..2047
    {
        dim3 grid(RDIM / BN, MDIM / BM);    // (16, 128)
        gemm_2p<<<grid, 128, SMEM2P>>>(pxhi, pxlo, pw6hi, HDIM, pP, PW);
    }
    // GEMM1-rest: 1-pass, cols 2048..12287 (q / gc / h)
    // actlut (global region nibbles): r1 q=0, r2,3 gc=4, r4,5 h=5 -> 0x554400
    {
        dim3 grid((NPROJ - RDIM) / BN, MDIM / BM);   // (80, 128)
        gemm_1p<<<grid, 128, SMEM1P>>>(pxhi, pw6hi + (size_t)RDIM * HDIM, HDIM,
                                       pP, PW, pa2, 0x554400u, RDIM);
    }

    // scan
    {
        dim3 gA(RDIM / 256, 4 * NCH);
        scanA_kernel<<<gA, 256>>>(pP, pFc, pGc);
        scanB_kernel<<<32, 256>>>(pFc, pGc, init, pSc);
        scanC_kernel<<<gA, 256>>>(pP, pSc, pa2);
    }

    // GEMM2: out = [ro | h] @ Wout^T, single-pass fp16
    {
        dim3 grid(HDIM / BN, MDIM / BM);    // (8, 128)
        gemm_1p<<<grid, 128, SMEM1P>>>(pa2, pwo, KOUT, out, HDIM, pa2, 0u, 0);
    }
}

// round 14
// speedup vs baseline: 2.2542x; 1.0776x over previous
#include <cuda_runtime.h>
#include <cuda_fp16.h>
#include <stdint.h>
#include <math.h>

// ---------------- problem dims ----------------
#define MDIM 8192      // B*S
#define HDIM 1024
#define RDIM 2048
#define SDIM 2048
#define NPROJ 12288    // 6 * 2048 stacked projection outputs (GEMM1 N)
#define PW 6144        // P width after pair fusion: f | q | gc
#define KOUT 4096      // R + L for the output GEMM
#define NCH 64         // scan chunks
#define CH 32          // tokens per chunk

// ---------------- scratch (device globals) ----------------
__device__ float   g_P   [(size_t)MDIM * PW];              // f | q | gc
__device__ __half  g_x16 [(size_t)MDIM * HDIM];
__device__ __half  g_w6  [(size_t)NPROJ * HDIM];
__device__ __half  g_wo  [(size_t)HDIM * KOUT];            // Wout single fp16
__device__ __half  g_a2  [(size_t)MDIM * KOUT];            // [ro | h], single fp16
__device__ float   g_Fc  [(size_t)4 * NCH * RDIM];
__device__ float   g_Gc  [(size_t)4 * NCH * RDIM];
__device__ float   g_Sc  [(size_t)4 * NCH * RDIM];

// ---------------- helpers ----------------
__device__ __forceinline__ uint32_t smem_u32(const void* p) {
    uint32_t a;
    asm("{ .reg .u64 t; cvta.to.shared.u64 t, %1; cvt.u32.u64 %0, t; }" : "=r"(a) : "l"(p));
    return a;
}
__device__ __forceinline__ void cp16(uint32_t s, const void* g) {
    asm volatile("cp.async.cg.shared.global [%0], [%1], 16;" :: "r"(s), "l"(g));
}
#define CP_COMMIT() asm volatile("cp.async.commit_group;" ::: "memory")
template<int N> __device__ __forceinline__ void cp_wait() {
    asm volatile("cp.async.wait_group %0;" :: "n"(N) : "memory");
}

__device__ __forceinline__ void ldm_x4(uint32_t (&d)[4], uint32_t a) {
    asm volatile("ldmatrix.sync.aligned.m8n8.x4.shared.b16 {%0,%1,%2,%3}, [%4];"
        : "=r"(d[0]), "=r"(d[1]), "=r"(d[2]), "=r"(d[3]) : "r"(a));
}
__device__ __forceinline__ void mma_f16(float (&c)[4], const uint32_t (&a)[4], const uint32_t* b) {
    asm volatile("mma.sync.aligned.m16n8k16.row.col.f32.f16.f16.f32 "
        "{%0,%1,%2,%3}, {%4,%5,%6,%7}, {%8,%9}, {%0,%1,%2,%3};"
        : "+f"(c[0]), "+f"(c[1]), "+f"(c[2]), "+f"(c[3])
        : "r"(a[0]), "r"(a[1]), "r"(a[2]), "r"(a[3]), "r"(b[0]), "r"(b[1]));
}

// ---------------- activations ----------------
#define ACT_NONE 0
#define ACT_TANH 1
#define ACT_GC 4     // pair: sigmoid(even) * silu(odd)   -> P (single col)
#define ACT_H  5     // pair: even * silu(odd)            -> a2 fp16

__device__ __forceinline__ float act_apply(float x, int act) {
    if (act == ACT_TANH) return tanhf(x);
    return x;
}
__device__ __forceinline__ float silu_f(float x) { return x / (1.0f + __expf(-x)); }
__device__ __forceinline__ float pair_act(float a, float b, int act) {
    if (act == ACT_GC) return (1.0f / (1.0f + __expf(-a))) * silu_f(b);
    return a * silu_f(b);   // ACT_H
}

#define BN 128
#define KC 32
#define RSTR 80         // 64B row + 16B pad (20-bank stride, conflict-free)
#define BM 64

// ---------------- shared epilogue ----------------
__device__ __forceinline__ void epilogue_store(
    float (&acc)[4][4][4], int act, int bm, int bn, int colbase,
    int lane, int wn, float* C, int ldc, __half* aux)
{
    const int row0 = bm * BM + (lane >> 2);
    if (act < 4) {
        const int col0 = colbase + bn * BN + wn * 32 + 2 * (lane & 3);
#pragma unroll
        for (int mi = 0; mi < 4; mi++) {
#pragma unroll
            for (int nj = 0; nj < 4; nj++) {
                float2 v0, v1;
                v0.x = act_apply(acc[mi][nj][0], act);
                v0.y = act_apply(acc[mi][nj][1], act);
                v1.x = act_apply(acc[mi][nj][2], act);
                v1.y = act_apply(acc[mi][nj][3], act);
                size_t base = (size_t)(row0 + mi * 16) * ldc + col0 + nj * 8;
                *(float2*)(C + base)                   = v0;
                *(float2*)(C + base + (size_t)8 * ldc) = v1;
            }
        }
    } else {
        // pair regions: even/odd cols combined in-thread. Base from ACT
        // (gc/h each span TWO 2048-regions).
        const int pcbase = ((colbase + bn * BN) >> 1) - ((act == ACT_GC) ? 2048 : 4096);
        const int pc0 = pcbase + wn * 16 + (lane & 3);
#pragma unroll
        for (int mi = 0; mi < 4; mi++) {
#pragma unroll
            for (int nj = 0; nj < 4; nj++) {
                float v0 = pair_act(acc[mi][nj][0], acc[mi][nj][1], act);
                float v1 = pair_act(acc[mi][nj][2], acc[mi][nj][3], act);
                int pc = pc0 + nj * 4;
                int r  = row0 + mi * 16;
                if (act == ACT_GC) {
                    C[(size_t)r * ldc + 4096 + pc]       = v0;  // gc at P cols 4096..6144
                    C[(size_t)(r + 8) * ldc + 4096 + pc] = v1;
                } else {
                    aux[(size_t)r * KOUT + 2048 + pc]       = __float2half_rn(v0);
                    aux[(size_t)(r + 8) * KOUT + 2048 + pc] = __float2half_rn(v1);
                }
            }
        }
    }
}

// ================= slim 1-pass fp16 GEMM (all regions) =================
// C = act(A*B^T), single fp16 pass. OCC=4 -> reg cap 128, no spill.
__global__ void __launch_bounds__(128, 4)
gemm_1p(const __half* __restrict__ A, const __half* __restrict__ B,
        int K, float* __restrict__ C, int ldc,
        __half* __restrict__ aux, unsigned actlut, int colbase)
{
    constexpr uint32_t OFF_B = BM * RSTR;
    constexpr uint32_t SB    = (BM + 128) * RSTR;     // 15360

    extern __shared__ char smem[];
    const uint32_t sbase = smem_u32(smem);
    const int tid = threadIdx.x;
    const int bm  = blockIdx.y, bn = blockIdx.x;
    const int wn  = tid >> 5, lane = tid & 31;

    const int region = (colbase + bn * BN) >> 11;
    const int act    = (int)((actlut >> (region * 4)) & 15u);

    const __half* sA = A + (size_t)bm * BM * K;
    const __half* sB = B + (size_t)bn * BN * K;

    const int lcol = tid & 3, lrow0 = tid >> 2;

    auto load_stage = [&](int s) {
        const uint32_t sb = sbase + (uint32_t)(s & 1) * SB + lcol * 16;
        const int k0 = s * KC + lcol * 8;
#pragma unroll
        for (int i = 0; i < 2; i++) {
            int row = lrow0 + 32 * i;
            cp16(sb + row * RSTR, sA + (size_t)row * K + k0);
        }
#pragma unroll
        for (int i = 0; i < 4; i++) {
            int row = lrow0 + 32 * i;
            cp16(sb + OFF_B + row * RSTR, sB + (size_t)row * K + k0);
        }
    };

    const int quad = lane >> 3, r8 = lane & 7;
    const uint32_t aoff = (uint32_t)((r8 + (quad & 1) * 8) * RSTR + (quad >> 1) * 16);
    const uint32_t boff = (uint32_t)(OFF_B + (wn * 32 + r8 + (quad >> 1) * 8) * RSTR + (quad & 1) * 16);

    float acc[4][4][4];
#pragma unroll
    for (int mi = 0; mi < 4; mi++)
#pragma unroll
        for (int nj = 0; nj < 4; nj++)
#pragma unroll
            for (int e = 0; e < 4; e++) acc[mi][nj][e] = 0.0f;

    const int ns = K / KC;
    load_stage(0); CP_COMMIT();

    for (int s = 0; s < ns; s++) {
        if (s + 1 < ns) load_stage(s + 1);
        CP_COMMIT();
        cp_wait<1>();
        __syncthreads();

        const uint32_t st = sbase + (uint32_t)(s & 1) * SB;
        const uint32_t aH = st + aoff;
        const uint32_t bH = st + boff;

#pragma unroll
        for (int ks = 0; ks < 2; ks++) {
            const uint32_t kb = ks * 32;
            uint32_t afh[4][4], bf[4][2];
#pragma unroll
            for (int mi = 0; mi < 4; mi++) ldm_x4(afh[mi], aH + mi * (16 * RSTR) + kb);
#pragma unroll
            for (int t = 0; t < 2; t++) {
                uint32_t tt[4];
                ldm_x4(tt, bH + t * (16 * RSTR) + kb);
                bf[2 * t][0] = tt[0]; bf[2 * t][1] = tt[1];
                bf[2 * t + 1][0] = tt[2]; bf[2 * t + 1][1] = tt[3];
            }
#pragma unroll
            for (int mi = 0; mi < 4; mi++)
#pragma unroll
                for (int nj = 0; nj < 4; nj++) mma_f16(acc[mi][nj], afh[mi], bf[nj]);
        }
        __syncthreads();
    }

    epilogue_store(acc, act, bm, bn, colbase, lane, wn, C, ldc, aux);
}

// ================= conversion kernels (plain fp16 casts) =================
__global__ void conv_x_kernel(const float* __restrict__ x, __half* __restrict__ o) {
    size_t i = (size_t)blockIdx.x * blockDim.x + threadIdx.x;
    o[i] = __float2half_rn(x[i]);
}

// W6 stacking: [f(0:2048) | q(2048:4096) | g:c interleaved(4096:8192) | up:gate interleaved(8192:12288)]
__global__ void conv_w6_kernel(const float* __restrict__ Wf, const float* __restrict__ Wi,
                               const float* __restrict__ Wv, const float* __restrict__ Wq,
                               const float* __restrict__ Wup, const float* __restrict__ Wg,
                               __half* __restrict__ o) {
    size_t i = (size_t)blockIdx.x * blockDim.x + threadIdx.x;     // [0, 12288*1024)
    int n = (int)(i >> 10);
    int k = (int)(i & 1023);
    const float* src;
    int r;
    if (n < 2048)       { src = Wf; r = n; }
    else if (n < 4096)  { src = Wq; r = n - 2048; }
    else if (n < 8192)  { r = (n - 4096) >> 1; src = (n & 1) ? Wv : Wi; }
    else                { r = (n - 8192) >> 1; src = (n & 1) ? Wg : Wup; }
    o[i] = __float2half_rn(src[(size_t)r * 1024 + k]);
}

__global__ void conv_wout_kernel(const float* __restrict__ Wro, const float* __restrict__ Wd,
                                 __half* __restrict__ w) {
    size_t i = (size_t)blockIdx.x * blockDim.x + threadIdx.x;     // [0, 1024*4096)
    int h = (int)(i >> 12);
    int j = (int)(i & 4095);
    float v = (j < 2048) ? Wro[(size_t)h * 2048 + j] : Wd[(size_t)h * 2048 + (j - 2048)];
    w[i] = __float2half_rn(v);
}

// ================= scan (two-level, chunked) =================
// P cols: f[0:2048)  q[2048:4096)  gc[4096:6144)
__global__ void scanA_kernel(const float* __restrict__ P,
                             float* __restrict__ Fc, float* __restrict__ Gc) {
    int r  = blockIdx.x * blockDim.x + threadIdx.x;
    int bc = blockIdx.y;
    int b = bc >> 6, ch = bc & 63;
    const float* row = P + (size_t)(b * SDIM + ch * CH) * PW;
    float F = 1.0f, G = 0.0f;
#pragma unroll 4
    for (int t = 0; t < CH; t++) {
        float f  = row[r];
        float gc = row[4096 + r];
        G = fmaf(f, G, gc);
        F *= f;
        row += PW;
    }
    Fc[(size_t)bc * RDIM + r] = F;
    Gc[(size_t)bc * RDIM + r] = G;
}

__global__ void scanB_kernel(const float* __restrict__ Fc, const float* __restrict__ Gc,
                             const float* __restrict__ init, float* __restrict__ Sc) {
    int i = blockIdx.x * blockDim.x + threadIdx.x;
    int b = i >> 11, r = i & 2047;
    float state = init[r];
    for (int ch = 0; ch < NCH; ch++) {
        size_t idx = (size_t)(b * NCH + ch) * RDIM + r;
        Sc[idx] = state;
        state = fmaf(Fc[idx], state, Gc[idx]);
    }
}

__global__ void scanC_kernel(const float* __restrict__ P, const float* __restrict__ Sc,
                             __half* __restrict__ a2) {
    int r  = blockIdx.x * blockDim.x + threadIdx.x;
    int bc = blockIdx.y;
    int b = bc >> 6, ch = bc & 63;
    int m0 = b * SDIM + ch * CH;
    const float* row = P + (size_t)m0 * PW;
    float state = Sc[(size_t)bc * RDIM + r];
#pragma unroll 4
    for (int t = 0; t < CH; t++) {
        float f  = row[r];
        float q  = row[2048 + r];
        float gc = row[4096 + r];
        state = fmaf(f, state, gc);
        float z = q * state;
        float ro = z / (1.0f + __expf(-z));
        a2[(size_t)(m0 + t) * KOUT + r] = __float2half_rn(ro);
        row += PW;
    }
}

// ================= launch =================
extern "C" void kernel_launch(void* const* d_in, const int* in_sizes, int n_in,
                              void* d_out, int out_size)
{
    const float* x    = (const float*)d_in[0];
    const float* Wf   = (const float*)d_in[1];
    const float* Wi   = (const float*)d_in[2];
    const float* Wv   = (const float*)d_in[3];
    const float* Wq   = (const float*)d_in[4];
    const float* Wro  = (const float*)d_in[5];
    const float* Wup  = (const float*)d_in[6];
    const float* Wg   = (const float*)d_in[7];
    const float* Wd   = (const float*)d_in[8];
    const float* init = (const float*)d_in[9];
    float* out = (float*)d_out;

    float *pP, *pFc, *pGc, *pSc;
    __half *px16, *pw6, *pwo, *pa2;
    cudaGetSymbolAddress((void**)&pP,   g_P);
    cudaGetSymbolAddress((void**)&px16, g_x16);
    cudaGetSymbolAddress((void**)&pw6,  g_w6);
    cudaGetSymbolAddress((void**)&pwo,  g_wo);
    cudaGetSymbolAddress((void**)&pa2,  g_a2);
    cudaGetSymbolAddress((void**)&pFc,  g_Fc);
    cudaGetSymbolAddress((void**)&pGc,  g_Gc);
    cudaGetSymbolAddress((void**)&pSc,  g_Sc);

    const int SMEM1P = (BM + 128) * RSTR * 2;      // 30720
    cudaFuncSetAttribute((const void*)gemm_1p,
                         cudaFuncAttributeMaxDynamicSharedMemorySize, SMEM1P);

    // conversions (plain casts)
    conv_x_kernel   <<<(MDIM * HDIM) / 256, 256>>>(x, px16);
    conv_w6_kernel  <<<(NPROJ * HDIM) / 256, 256>>>(Wf, Wi, Wv, Wq, Wup, Wg, pw6);
    conv_wout_kernel<<<(HDIM * KOUT) / 256, 256>>>(Wro, Wd, pwo);

    // GEMM1: all regions 1-pass. actlut nibbles: f=1(tanh) q=0 gc=4,4 h=5,5 -> 0x554401
    {
        dim3 grid(NPROJ / BN, MDIM / BM);   // (96, 128)
        gemm_1p<<<grid, 128, SMEM1P>>>(px16, pw6, HDIM, pP, PW, pa2, 0x554401u, 0);
    }

    // scan
    {
        dim3 gA(RDIM / 256, 4 * NCH);
        scanA_kernel<<<gA, 256>>>(pP, pFc, pGc);
        scanB_kernel<<<32, 256>>>(pFc, pGc, init, pSc);
        scanC_kernel<<<gA, 256>>>(pP, pSc, pa2);
    }

    // GEMM2: out = [ro | h] @ Wout^T, single-pass fp16
    {
        dim3 grid(HDIM / BN, MDIM / BM);    // (8, 128)
        gemm_1p<<<grid, 128, SMEM1P>>>(pa2, pwo, KOUT, out, HDIM, pa2, 0u, 0);
    }
}

// round 15
// speedup vs baseline: 2.5941x; 1.1507x over previous
#include <cuda_runtime.h>
#include <cuda_fp16.h>
#include <stdint.h>
#include <math.h>

// ---------------- problem dims ----------------
#define MDIM 8192      // B*S
#define HDIM 1024
#define RDIM 2048
#define SDIM 2048
#define NPROJ 12288    // 6 * 2048 stacked projection outputs (GEMM1 N)
#define PW 6144        // P width after pair fusion: f | q | gc
#define KOUT 4096      // R + L for the output GEMM
#define NCH 64         // scan chunks
#define CH 32          // tokens per chunk

// ---------------- scratch (device globals) ----------------
__device__ float   g_P   [(size_t)MDIM * PW];              // f | q | gc
__device__ __half  g_x16 [(size_t)MDIM * HDIM];
__device__ __half  g_w6  [(size_t)NPROJ * HDIM];
__device__ __half  g_wo  [(size_t)HDIM * KOUT];            // Wout single fp16
__device__ __half  g_a2  [(size_t)MDIM * KOUT];            // [ro | h], single fp16
__device__ float   g_Fc  [(size_t)4 * NCH * RDIM];
__device__ float   g_Gc  [(size_t)4 * NCH * RDIM];
__device__ float   g_Sc  [(size_t)4 * NCH * RDIM];

// ---------------- helpers ----------------
__device__ __forceinline__ uint32_t smem_u32(const void* p) {
    uint32_t a;
    asm("{ .reg .u64 t; cvta.to.shared.u64 t, %1; cvt.u32.u64 %0, t; }" : "=r"(a) : "l"(p));
    return a;
}
__device__ __forceinline__ void cp16(uint32_t s, const void* g) {
    asm volatile("cp.async.cg.shared.global [%0], [%1], 16;" :: "r"(s), "l"(g));
}
#define CP_COMMIT() asm volatile("cp.async.commit_group;" ::: "memory")
template<int N> __device__ __forceinline__ void cp_wait() {
    asm volatile("cp.async.wait_group %0;" :: "n"(N) : "memory");
}

__device__ __forceinline__ void ldm_x4(uint32_t (&d)[4], uint32_t a) {
    asm volatile("ldmatrix.sync.aligned.m8n8.x4.shared.b16 {%0,%1,%2,%3}, [%4];"
        : "=r"(d[0]), "=r"(d[1]), "=r"(d[2]), "=r"(d[3]) : "r"(a));
}
__device__ __forceinline__ void mma_f16(float (&c)[4], const uint32_t (&a)[4], const uint32_t* b) {
    asm volatile("mma.sync.aligned.m16n8k16.row.col.f32.f16.f16.f32 "
        "{%0,%1,%2,%3}, {%4,%5,%6,%7}, {%8,%9}, {%0,%1,%2,%3};"
        : "+f"(c[0]), "+f"(c[1]), "+f"(c[2]), "+f"(c[3])
        : "r"(a[0]), "r"(a[1]), "r"(a[2]), "r"(a[3]), "r"(b[0]), "r"(b[1]));
}

// ---------------- activations ----------------
#define ACT_NONE 0
#define ACT_TANH 1
#define ACT_GC 4     // pair: sigmoid(even) * silu(odd)   -> P (single col)
#define ACT_H  5     // pair: even * silu(odd)            -> a2 fp16

__device__ __forceinline__ float act_apply(float x, int act) {
    if (act == ACT_TANH) return tanhf(x);
    return x;
}
__device__ __forceinline__ float silu_f(float x) { return x / (1.0f + __expf(-x)); }
__device__ __forceinline__ float pair_act(float a, float b, int act) {
    if (act == ACT_GC) return (1.0f / (1.0f + __expf(-a))) * silu_f(b);
    return a * silu_f(b);   // ACT_H
}

#define BN 128
#define KC 64
#define RSTR 144        // 128B row + 16B pad (conflict-free, validated r3-r5)
#define BM 64

// ---------------- shared epilogue ----------------
__device__ __forceinline__ void epilogue_store(
    float (&acc)[4][4][4], int act, int bm, int bn, int colbase,
    int lane, int wn, float* C, int ldc, __half* aux)
{
    const int row0 = bm * BM + (lane >> 2);
    if (act < 4) {
        const int col0 = colbase + bn * BN + wn * 32 + 2 * (lane & 3);
#pragma unroll
        for (int mi = 0; mi < 4; mi++) {
#pragma unroll
            for (int nj = 0; nj < 4; nj++) {
                float2 v0, v1;
                v0.x = act_apply(acc[mi][nj][0], act);
                v0.y = act_apply(acc[mi][nj][1], act);
                v1.x = act_apply(acc[mi][nj][2], act);
                v1.y = act_apply(acc[mi][nj][3], act);
                size_t base = (size_t)(row0 + mi * 16) * ldc + col0 + nj * 8;
                *(float2*)(C + base)                   = v0;
                *(float2*)(C + base + (size_t)8 * ldc) = v1;
            }
        }
    } else {
        // pair regions: even/odd cols combined in-thread. Base from ACT
        // (gc/h each span TWO 2048-regions).
        const int pcbase = ((colbase + bn * BN) >> 1) - ((act == ACT_GC) ? 2048 : 4096);
        const int pc0 = pcbase + wn * 16 + (lane & 3);
#pragma unroll
        for (int mi = 0; mi < 4; mi++) {
#pragma unroll
            for (int nj = 0; nj < 4; nj++) {
                float v0 = pair_act(acc[mi][nj][0], acc[mi][nj][1], act);
                float v1 = pair_act(acc[mi][nj][2], acc[mi][nj][3], act);
                int pc = pc0 + nj * 4;
                int r  = row0 + mi * 16;
                if (act == ACT_GC) {
                    C[(size_t)r * ldc + 4096 + pc]       = v0;  // gc at P cols 4096..6144
                    C[(size_t)(r + 8) * ldc + 4096 + pc] = v1;
                } else {
                    aux[(size_t)r * KOUT + 2048 + pc]       = __float2half_rn(v0);
                    aux[(size_t)(r + 8) * KOUT + 2048 + pc] = __float2half_rn(v1);
                }
            }
        }
    }
}

// ================= slim 1-pass fp16 GEMM, KC=64 =================
// C = act(A*B^T), single fp16 pass. 64 HMMA/stage (2x the KC=32 version) to
// amortize per-stage sync + cp.async overhead. OCC=4 -> reg cap 128.
__global__ void __launch_bounds__(128, 4)
gemm_1p(const __half* __restrict__ A, const __half* __restrict__ B,
        int K, float* __restrict__ C, int ldc,
        __half* __restrict__ aux, unsigned actlut, int colbase)
{
    constexpr uint32_t OFF_B = BM * RSTR;
    constexpr uint32_t SB    = (BM + 128) * RSTR;     // 27648

    extern __shared__ char smem[];
    const uint32_t sbase = smem_u32(smem);
    const int tid = threadIdx.x;
    const int bm  = blockIdx.y, bn = blockIdx.x;
    const int wn  = tid >> 5, lane = tid & 31;

    const int region = (colbase + bn * BN) >> 11;
    const int act    = (int)((actlut >> (region * 4)) & 15u);

    const __half* sA = A + (size_t)bm * BM * K;
    const __half* sB = B + (size_t)bn * BN * K;

    const int lcol = tid & 7, lrow0 = tid >> 3;     // 8 x 16B chunks per 128B row

    auto load_stage = [&](int s) {
        const uint32_t sb = sbase + (uint32_t)(s & 1) * SB + lcol * 16;
        const int k0 = s * KC + lcol * 8;
#pragma unroll
        for (int i = 0; i < 4; i++) {               // A: 64 rows
            int row = lrow0 + 16 * i;
            cp16(sb + row * RSTR, sA + (size_t)row * K + k0);
        }
#pragma unroll
        for (int i = 0; i < 8; i++) {               // B: 128 rows
            int row = lrow0 + 16 * i;
            cp16(sb + OFF_B + row * RSTR, sB + (size_t)row * K + k0);
        }
    };

    const int quad = lane >> 3, r8 = lane & 7;
    const uint32_t aoff = (uint32_t)((r8 + (quad & 1) * 8) * RSTR + (quad >> 1) * 16);
    const uint32_t boff = (uint32_t)(OFF_B + (wn * 32 + r8 + (quad >> 1) * 8) * RSTR + (quad & 1) * 16);

    float acc[4][4][4];
#pragma unroll
    for (int mi = 0; mi < 4; mi++)
#pragma unroll
        for (int nj = 0; nj < 4; nj++)
#pragma unroll
            for (int e = 0; e < 4; e++) acc[mi][nj][e] = 0.0f;

    const int ns = K / KC;
    load_stage(0); CP_COMMIT();

    for (int s = 0; s < ns; s++) {
        if (s + 1 < ns) load_stage(s + 1);
        CP_COMMIT();
        cp_wait<1>();
        __syncthreads();

        const uint32_t st = sbase + (uint32_t)(s & 1) * SB;
        const uint32_t aH = st + aoff;
        const uint32_t bH = st + boff;

#pragma unroll
        for (int ks = 0; ks < 4; ks++) {
            const uint32_t kb = ks * 32;
            uint32_t afh[4][4], bf[4][2];
#pragma unroll
            for (int mi = 0; mi < 4; mi++) ldm_x4(afh[mi], aH + mi * (16 * RSTR) + kb);
#pragma unroll
            for (int t = 0; t < 2; t++) {
                uint32_t tt[4];
                ldm_x4(tt, bH + t * (16 * RSTR) + kb);
                bf[2 * t][0] = tt[0]; bf[2 * t][1] = tt[1];
                bf[2 * t + 1][0] = tt[2]; bf[2 * t + 1][1] = tt[3];
            }
#pragma unroll
            for (int mi = 0; mi < 4; mi++)
#pragma unroll
                for (int nj = 0; nj < 4; nj++) mma_f16(acc[mi][nj], afh[mi], bf[nj]);
        }
        __syncthreads();
    }

    epilogue_store(acc, act, bm, bn, colbase, lane, wn, C, ldc, aux);
}

// ================= conversion kernels (plain fp16 casts) =================
__global__ void conv_x_kernel(const float* __restrict__ x, __half* __restrict__ o) {
    size_t i = (size_t)blockIdx.x * blockDim.x + threadIdx.x;
    o[i] = __float2half_rn(x[i]);
}

// W6 stacking: [f(0:2048) | q(2048:4096) | g:c interleaved(4096:8192) | up:gate interleaved(8192:12288)]
__global__ void conv_w6_kernel(const float* __restrict__ Wf, const float* __restrict__ Wi,
                               const float* __restrict__ Wv, const float* __restrict__ Wq,
                               const float* __restrict__ Wup, const float* __restrict__ Wg,
                               __half* __restrict__ o) {
    size_t i = (size_t)blockIdx.x * blockDim.x + threadIdx.x;     // [0, 12288*1024)
    int n = (int)(i >> 10);
    int k = (int)(i & 1023);
    const float* src;
    int r;
    if (n < 2048)       { src = Wf; r = n; }
    else if (n < 4096)  { src = Wq; r = n - 2048; }
    else if (n < 8192)  { r = (n - 4096) >> 1; src = (n & 1) ? Wv : Wi; }
    else                { r = (n - 8192) >> 1; src = (n & 1) ? Wg : Wup; }
    o[i] = __float2half_rn(src[(size_t)r * 1024 + k]);
}

__global__ void conv_wout_kernel(const float* __restrict__ Wro, const float* __restrict__ Wd,
                                 __half* __restrict__ w) {
    size_t i = (size_t)blockIdx.x * blockDim.x + threadIdx.x;     // [0, 1024*4096)
    int h = (int)(i >> 12);
    int j = (int)(i & 4095);
    float v = (j < 2048) ? Wro[(size_t)h * 2048 + j] : Wd[(size_t)h * 2048 + (j - 2048)];
    w[i] = __float2half_rn(v);
}

// ================= scan (two-level, chunked) =================
// P cols: f[0:2048)  q[2048:4096)  gc[4096:6144)
__global__ void scanA_kernel(const float* __restrict__ P,
                             float* __restrict__ Fc, float* __restrict__ Gc) {
    int r  = blockIdx.x * blockDim.x + threadIdx.x;
    int bc = blockIdx.y;
    int b = bc >> 6, ch = bc & 63;
    const float* row = P + (size_t)(b * SDIM + ch * CH) * PW;
    float F = 1.0f, G = 0.0f;
#pragma unroll 4
    for (int t = 0; t < CH; t++) {
        float f  = row[r];
        float gc = row[4096 + r];
        G = fmaf(f, G, gc);
        F *= f;
        row += PW;
    }
    Fc[(size_t)bc * RDIM + r] = F;
    Gc[(size_t)bc * RDIM + r] = G;
}

__global__ void scanB_kernel(const float* __restrict__ Fc, const float* __restrict__ Gc,
                             const float* __restrict__ init, float* __restrict__ Sc) {
    int i = blockIdx.x * blockDim.x + threadIdx.x;
    int b = i >> 11, r = i & 2047;
    float state = init[r];
    for (int ch = 0; ch < NCH; ch++) {
        size_t idx = (size_t)(b * NCH + ch) * RDIM + r;
        Sc[idx] = state;
        state = fmaf(Fc[idx], state, Gc[idx]);
    }
}

__global__ void scanC_kernel(const float* __restrict__ P, const float* __restrict__ Sc,
                             __half* __restrict__ a2) {
    int r  = blockIdx.x * blockDim.x + threadIdx.x;
    int bc = blockIdx.y;
    int b = bc >> 6, ch = bc & 63;
    int m0 = b * SDIM + ch * CH;
    const float* row = P + (size_t)m0 * PW;
    float state = Sc[(size_t)bc * RDIM + r];
#pragma unroll 4
    for (int t = 0; t < CH; t++) {
        float f  = row[r];
        float q  = row[2048 + r];
        float gc = row[4096 + r];
        state = fmaf(f, state, gc);
        float z = q * state;
        float ro = z / (1.0f + __expf(-z));
        a2[(size_t)(m0 + t) * KOUT + r] = __float2half_rn(ro);
        row += PW;
    }
}

// ================= launch =================
extern "C" void kernel_launch(void* const* d_in, const int* in_sizes, int n_in,
                              void* d_out, int out_size)
{
    const float* x    = (const float*)d_in[0];
    const float* Wf   = (const float*)d_in[1];
    const float* Wi   = (const float*)d_in[2];
    const float* Wv   = (const float*)d_in[3];
    const float* Wq   = (const float*)d_in[4];
    const float* Wro  = (const float*)d_in[5];
    const float* Wup  = (const float*)d_in[6];
    const float* Wg   = (const float*)d_in[7];
    const float* Wd   = (const float*)d_in[8];
    const float* init = (const float*)d_in[9];
    float* out = (float*)d_out;

    float *pP, *pFc, *pGc, *pSc;
    __half *px16, *pw6, *pwo, *pa2;
    cudaGetSymbolAddress((void**)&pP,   g_P);
    cudaGetSymbolAddress((void**)&px16, g_x16);
    cudaGetSymbolAddress((void**)&pw6,  g_w6);
    cudaGetSymbolAddress((void**)&pwo,  g_wo);
    cudaGetSymbolAddress((void**)&pa2,  g_a2);
    cudaGetSymbolAddress((void**)&pFc,  g_Fc);
    cudaGetSymbolAddress((void**)&pGc,  g_Gc);
    cudaGetSymbolAddress((void**)&pSc,  g_Sc);

    const int SMEM1P = (BM + 128) * RSTR * 2;      // 55296; 4 CTAs/SM = 221184
    cudaFuncSetAttribute((const void*)gemm_1p,
                         cudaFuncAttributeMaxDynamicSharedMemorySize, SMEM1P);

    // conversions (plain casts)
    conv_x_kernel   <<<(MDIM * HDIM) / 256, 256>>>(x, px16);
    conv_w6_kernel  <<<(NPROJ * HDIM) / 256, 256>>>(Wf, Wi, Wv, Wq, Wup, Wg, pw6);
    conv_wout_kernel<<<(HDIM * KOUT) / 256, 256>>>(Wro, Wd, pwo);

    // GEMM1: all regions 1-pass. actlut nibbles: f=1(tanh) q=0 gc=4,4 h=5,5 -> 0x554401
    {
        dim3 grid(NPROJ / BN, MDIM / BM);   // (96, 128)
        gemm_1p<<<grid, 128, SMEM1P>>>(px16, pw6, HDIM, pP, PW, pa2, 0x554401u, 0);
    }

    // scan
    {
        dim3 gA(RDIM / 256, 4 * NCH);
        scanA_kernel<<<gA, 256>>>(pP, pFc, pGc);
        scanB_kernel<<<32, 256>>>(pFc, pGc, init, pSc);
        scanC_kernel<<<gA, 256>>>(pP, pSc, pa2);
    }

    // GEMM2: out = [ro | h] @ Wout^T, single-pass fp16
    {
        dim3 grid(HDIM / BN, MDIM / BM);    // (8, 128)
        gemm_1p<<<grid, 128, SMEM1P>>>(pa2, pwo, KOUT, out, HDIM, pa2, 0u, 0);
    }
}